// round 13
// baseline (speedup 1.0000x reference)
#include <cuda_runtime.h>
#include <cuda_fp16.h>
#include <math.h>
#include <stdint.h>

#define TOK   4096
#define DIM   1024
#define MLPD  4096
#define NHEAD 16
#define HD    64
#define SEQ   2048

// ---------------- scratch ----------------
__device__ float g_x1  [TOK * DIM];
__device__ __half g_xln [TOK * DIM];
__device__ __half g_q   [TOK * DIM];   // Q (scaled)
__device__ __half g_k   [TOK * DIM];   // K
__device__ __half g_v   [TOK * DIM];   // V
__device__ __half g_attn[TOK * DIM];
__device__ __half g_xln2[TOK * DIM];
__device__ __half g_h   [TOK * MLPD];
__device__ __half g_wqkv[3 * DIM * DIM];
__device__ __half g_wout[DIM * DIM];
__device__ __half g_w1  [MLPD * DIM];
__device__ __half g_w2  [DIM * MLPD];

// ---------------- helpers ----------------
__device__ __forceinline__ uint32_t cvt2h(float x, float y) {
    __half2 h = __floats2half2_rn(x, y);
    return *(uint32_t*)&h;
}

__device__ __forceinline__ void mma_f16(float* d,
    uint32_t a0, uint32_t a1, uint32_t a2, uint32_t a3,
    uint32_t b0, uint32_t b1)
{
    asm volatile(
        "mma.sync.aligned.m16n8k16.row.col.f32.f16.f16.f32 "
        "{%0,%1,%2,%3}, {%4,%5,%6,%7}, {%8,%9}, {%0,%1,%2,%3};"
        : "+f"(d[0]), "+f"(d[1]), "+f"(d[2]), "+f"(d[3])
        : "r"(a0), "r"(a1), "r"(a2), "r"(a3), "r"(b0), "r"(b1));
}

#define LDSM4(R0,R1,R2,R3,ADDR) \
    asm volatile("ldmatrix.sync.aligned.m8n8.x4.shared.b16 {%0,%1,%2,%3}, [%4];" \
        : "=r"(R0), "=r"(R1), "=r"(R2), "=r"(R3) : "r"(ADDR))

#define CP16(dst, src) \
    asm volatile("cp.async.ca.shared.global [%0], [%1], 16;" :: "r"(dst), "l"(src) : "memory")
#define CP_COMMIT() asm volatile("cp.async.commit_group;" ::: "memory")
#define CP_WAIT1()  asm volatile("cp.async.wait_group 1;" ::: "memory")

// ---------------- merged weight convert (fp32 -> fp16) ----------------
#define CB0 (3 * DIM * DIM / 4)
#define CB1 (CB0 + DIM * DIM / 4)
#define CB2 (CB1 + MLPD * DIM / 4)
#define CB3 (CB2 + DIM * MLPD / 4)

__global__ __launch_bounds__(256) void conv_all(
    const float* __restrict__ s0, const float* __restrict__ s1,
    const float* __restrict__ s2, const float* __restrict__ s3,
    __half* __restrict__ d0, __half* __restrict__ d1,
    __half* __restrict__ d2, __half* __restrict__ d3)
{
    int i0 = blockIdx.x * 1024 + threadIdx.x;
    #pragma unroll
    for (int k2 = 0; k2 < 4; ++k2) {
        int i = i0 + k2 * 256;
        if (i < CB3) {
            const float* sp; __half* dp; int off;
            if (i < CB0)      { sp = s0; dp = d0; off = i; }
            else if (i < CB1) { sp = s1; dp = d1; off = i - CB0; }
            else if (i < CB2) { sp = s2; dp = d2; off = i - CB1; }
            else              { sp = s3; dp = d3; off = i - CB2; }
            float4 v = ((const float4*)sp)[off];
            ((uint2*)dp)[off] = make_uint2(cvt2h(v.x, v.y), cvt2h(v.z, v.w));
        }
    }
}

// ---------------- LayerNorm, warp-per-row ----------------
__global__ __launch_bounds__(256) void ln_kernel(
    const float* __restrict__ x, const float* __restrict__ w,
    const float* __restrict__ b, __half* __restrict__ o)
{
    int warp = threadIdx.x >> 5, lane = threadIdx.x & 31;
    int row = blockIdx.x * 8 + warp;
    const float4* xr = (const float4*)(x + (size_t)row * DIM);
    float4 v[8];
    float s = 0.f, sq = 0.f;
    #pragma unroll
    for (int i = 0; i < 8; i++) {
        v[i] = xr[lane + i * 32];
        s  += v[i].x + v[i].y + v[i].z + v[i].w;
        sq += v[i].x*v[i].x + v[i].y*v[i].y + v[i].z*v[i].z + v[i].w*v[i].w;
    }
    #pragma unroll
    for (int of = 16; of > 0; of >>= 1) {
        s  += __shfl_xor_sync(0xffffffffu, s,  of);
        sq += __shfl_xor_sync(0xffffffffu, sq, of);
    }
    float mean = s * (1.0f / DIM);
    float rstd = rsqrtf(sq * (1.0f / DIM) - mean * mean + 1e-5f);
    uint2* orow = (uint2*)o + (size_t)row * (DIM / 4);
    #pragma unroll
    for (int i = 0; i < 8; i++) {
        int idx = lane + i * 32;
        float4 wv = ((const float4*)w)[idx];
        float4 bv = ((const float4*)b)[idx];
        float ox = (v[i].x - mean) * rstd * wv.x + bv.x;
        float oy = (v[i].y - mean) * rstd * wv.y + bv.y;
        float oz = (v[i].z - mean) * rstd * wv.z + bv.z;
        float ow = (v[i].w - mean) * rstd * wv.w + bv.w;
        orow[idx] = make_uint2(cvt2h(ox, oy), cvt2h(oz, ow));
    }
}

// ---------------- NT GEMM fp16, KT=64, 3-stage cp.async, ldmatrix ----------
#define EPI_NONE      0
#define EPI_BIAS_RES  1
#define EPI_SILU_H    2
#define EPI_QKV       3

#define WST2 36                       // words per smem row (32 data + 4 pad) = 144B
#define PLW2 (128 * WST2)             // words per plane
#define STGW2 (2 * PLW2)              // A, W
#define NSTAGE 3
#define GEMM_SMEM (NSTAGE * STGW2 * 4)   // 110592

template <int EPI>
__global__ __launch_bounds__(256, 2) void gemm_f16(
    const __half* __restrict__ A, const __half* __restrict__ W,
    const float* __restrict__ bias, const float* __restrict__ res,
    float* __restrict__ C,
    __half* __restrict__ H0, __half* __restrict__ H1, __half* __restrict__ H2,
    int M, int N, int K)
{
    extern __shared__ __align__(16) uint32_t smw[];
    uint32_t sbase = (uint32_t)__cvta_generic_to_shared(smw);

    int tid  = threadIdx.x;
    int warp = tid >> 5, lane = tid & 31;
    int bm   = blockIdx.y * 128;
    int bn   = blockIdx.x * 128;
    int wm   = (warp & 1) * 64;
    int wn   = (warp >> 1) * 32;
    int gid  = lane >> 2, tig = lane & 3;

    int lrow  = tid >> 1;
    int lh    = tid & 1;                 // 32-half (64B) chunk
    const __half* pA = A + (size_t)(bm + lrow) * K + lh * 32;
    const __half* pW = W + (size_t)(bn + lrow) * K + lh * 32;
    uint32_t dstb = (uint32_t)(lrow * WST2 + lh * 16) * 4;

    uint32_t a_off = (uint32_t)(((wm + (lane & 15)) * WST2 + (lane >> 4) * 4) * 4);
    uint32_t b_off = (uint32_t)(((wn + ((lane >> 4) & 1) * 8 + (lane & 7)) * WST2
                                 + ((lane >> 3) & 1) * 4) * 4);

    float acc[4][4][4];
    #pragma unroll
    for (int i = 0; i < 4; i++)
        #pragma unroll
        for (int j = 0; j < 4; j++)
            #pragma unroll
            for (int r = 0; r < 4; r++) acc[i][j][r] = 0.f;

    int ntiles = K >> 6;

    auto issue = [&](int t) {
        uint32_t base = sbase + ((t % NSTAGE) * STGW2) * 4 + dstb;
        const __half* a = pA + (size_t)t * 64;
        const __half* w = pW + (size_t)t * 64;
        #pragma unroll
        for (int c = 0; c < 4; ++c) {
            CP16(base + c * 16,          a + c * 8);
            CP16(base + PLW2*4 + c * 16, w + c * 8);
        }
    };

    issue(0); CP_COMMIT();
    issue(1); CP_COMMIT();

    for (int t = 0; t < ntiles; ++t) {
        CP_WAIT1();
        __syncthreads();
        uint32_t stb = sbase + ((t % NSTAGE) * STGW2) * 4;

        #pragma unroll
        for (int kc = 0; kc < 4; ++kc) {
            uint32_t kcb = kc * 32;
            uint32_t bw[4][2];
            #pragma unroll
            for (int p = 0; p < 2; ++p) {
                uint32_t r0, r1, r2, r3;
                LDSM4(r0, r1, r2, r3, stb + PLW2*4 + b_off + p * 16 * WST2 * 4 + kcb);
                bw[2*p][0] = r0; bw[2*p][1] = r1; bw[2*p+1][0] = r2; bw[2*p+1][1] = r3;
            }
            #pragma unroll
            for (int mt = 0; mt < 4; ++mt) {
                uint32_t a0, a1, a2, a3;
                LDSM4(a0, a1, a2, a3, stb + a_off + mt * 16 * WST2 * 4 + kcb);
                #pragma unroll
                for (int nt = 0; nt < 4; ++nt)
                    mma_f16(acc[mt][nt], a0, a1, a2, a3, bw[nt][0], bw[nt][1]);
            }
        }
        if (t + 2 < ntiles) issue(t + 2);
        CP_COMMIT();
    }

    // ---- epilogue ----
    #pragma unroll
    for (int mt = 0; mt < 4; ++mt) {
        #pragma unroll
        for (int nt = 0; nt < 4; ++nt) {
            int row = bm + wm + mt * 16 + gid;
            int col = bn + wn + nt * 8 + tig * 2;
            float2 v0 = make_float2(acc[mt][nt][0], acc[mt][nt][1]);
            float2 v1 = make_float2(acc[mt][nt][2], acc[mt][nt][3]);
            if (EPI == EPI_BIAS_RES || EPI == EPI_SILU_H) {
                float bx = bias[col], by = bias[col + 1];
                v0.x += bx; v0.y += by; v1.x += bx; v1.y += by;
            }
            if (EPI == EPI_BIAS_RES) {
                float2 r0 = *(const float2*)(res + (size_t)row * N + col);
                float2 r1 = *(const float2*)(res + (size_t)(row + 8) * N + col);
                v0.x += r0.x; v0.y += r0.y; v1.x += r1.x; v1.y += r1.y;
                *(float2*)(C + (size_t)row * N + col)       = v0;
                *(float2*)(C + (size_t)(row + 8) * N + col) = v1;
            } else if (EPI == EPI_SILU_H) {
                v0.x *= 1.f / (1.f + __expf(-v0.x));
                v0.y *= 1.f / (1.f + __expf(-v0.y));
                v1.x *= 1.f / (1.f + __expf(-v1.x));
                v1.y *= 1.f / (1.f + __expf(-v1.y));
                *(uint32_t*)(H0 + (size_t)row * N + col)       = cvt2h(v0.x, v0.y);
                *(uint32_t*)(H0 + (size_t)(row + 8) * N + col) = cvt2h(v1.x, v1.y);
            } else if (EPI == EPI_QKV) {
                int region = col >> 10;
                int colr   = col & 1023;
                __half* dst = (region == 0) ? H0 : (region == 1) ? H1 : H2;
                float sc = (region == 0) ? 0.125f : 1.0f;
                *(uint32_t*)(dst + (size_t)row * DIM + colr) =
                    cvt2h(v0.x * sc, v0.y * sc);
                *(uint32_t*)(dst + (size_t)(row + 8) * DIM + colr) =
                    cvt2h(v1.x * sc, v1.y * sc);
            } else {
                *(float2*)(C + (size_t)row * N + col)       = v0;
                *(float2*)(C + (size_t)(row + 8) * N + col) = v1;
            }
        }
    }
}

// ---------------- Flash attention fp16, hoisted Q frags, K/V prefetch ------
#define AST 36
#define W_Q 0
#define W_K (W_Q + 128 * AST)                 // double-buffered: 2 x 64 rows
#define W_V (W_K + 2 * 64 * AST)
#define ATTN_WORDS (W_V + 2 * 64 * AST)
#define ATTN_SM_BYTES (ATTN_WORDS * 4)        // 55296

__global__ __launch_bounds__(256, 2) void attn_f16(
    const __half* __restrict__ Qg, const __half* __restrict__ Kg,
    const __half* __restrict__ Vg, __half* __restrict__ o)
{
    extern __shared__ uint32_t smw[];
    uint32_t sbase = (uint32_t)__cvta_generic_to_shared(smw);
    uint32_t* Qs = smw + W_Q;
    uint32_t* Kb = smw + W_K;
    uint32_t* Vb = smw + W_V;

    int tid  = threadIdx.x;
    int warp = tid >> 5, lane = tid & 31;
    int gid  = lane >> 2, tig = lane & 3;
    int qrow0 = warp * 16;

    int qb = blockIdx.x;
    int b  = blockIdx.y >> 4;
    int h  = blockIdx.y & 15;

    uint32_t aoff = (uint32_t)((((lane & 15)) * AST + (lane >> 4) * 4) * 4);
    uint32_t boff = (uint32_t)(((((lane >> 4) & 1) * 8 + (lane & 7)) * AST
                                + ((lane >> 3) & 1) * 4) * 4);

    int kr = tid >> 3, kc = (tid & 7) * 8;
    int vr = tid >> 4, vc = (tid & 15) * 4;

    const __half* kbase = Kg + (size_t)(b * SEQ) * DIM + h * HD;
    const __half* vbase = Vg + (size_t)(b * SEQ) * DIM + h * HD;

    uint4 kA, kB;
    uint2 vA0, vA1, vB0, vB1;
    auto ldgKV = [&](int jb) {
        const __half* kg = kbase + (size_t)(jb * 64) * DIM;
        const __half* vg = vbase + (size_t)(jb * 64) * DIM;
        kA = *(const uint4*)(kg + (size_t)kr * DIM + kc);
        kB = *(const uint4*)(kg + (size_t)(kr + 32) * DIM + kc);
        vA0 = *(const uint2*)(vg + (size_t)(2 * vr) * DIM + vc);
        vA1 = *(const uint2*)(vg + (size_t)(2 * vr + 1) * DIM + vc);
        vB0 = *(const uint2*)(vg + (size_t)(2 * (vr + 16)) * DIM + vc);
        vB1 = *(const uint2*)(vg + (size_t)(2 * (vr + 16) + 1) * DIM + vc);
    };
    auto stsKV = [&](int buf) {
        uint32_t* kp = Kb + buf * 64 * AST;
        *(uint4*)(kp + kr * AST + (kc >> 1))        = kA;
        *(uint4*)(kp + (kr + 32) * AST + (kc >> 1)) = kB;
        uint32_t* vp = Vb + buf * 64 * AST;
        vp[(vc + 0) * AST + vr] = __byte_perm(vA0.x, vA1.x, 0x5410);
        vp[(vc + 1) * AST + vr] = __byte_perm(vA0.x, vA1.x, 0x7632);
        vp[(vc + 2) * AST + vr] = __byte_perm(vA0.y, vA1.y, 0x5410);
        vp[(vc + 3) * AST + vr] = __byte_perm(vA0.y, vA1.y, 0x7632);
        vp[(vc + 0) * AST + vr + 16] = __byte_perm(vB0.x, vB1.x, 0x5410);
        vp[(vc + 1) * AST + vr + 16] = __byte_perm(vB0.x, vB1.x, 0x7632);
        vp[(vc + 2) * AST + vr + 16] = __byte_perm(vB0.y, vB1.y, 0x5410);
        vp[(vc + 3) * AST + vr + 16] = __byte_perm(vB0.y, vB1.y, 0x7632);
    };

    // prologue: start K/V(0) loads, fill Q, hoist Q fragments
    ldgKV(0);
    {
        const __half* qg = Qg + (size_t)(b * SEQ + qb * 128) * DIM + h * HD;
        for (int e = tid; e < 128 * 8; e += 256) {
            int r = e >> 3, c = (e & 7) * 8;
            uint4 v = *(const uint4*)(qg + (size_t)r * DIM + c);
            *(uint4*)(Qs + r * AST + (c >> 1)) = v;
        }
    }
    __syncthreads();
    uint32_t qf[4][4];
    #pragma unroll
    for (int kcx = 0; kcx < 4; ++kcx)
        LDSM4(qf[kcx][0], qf[kcx][1], qf[kcx][2], qf[kcx][3],
              sbase + (W_Q + qrow0 * AST) * 4 + aoff + kcx * 32);

    float m0 = -1e30f, m1 = -1e30f, l0r = 0.f, l1r = 0.f;
    float oacc[8][4];
    #pragma unroll
    for (int nt = 0; nt < 8; nt++)
        #pragma unroll
        for (int r = 0; r < 4; r++) oacc[nt][r] = 0.f;

    for (int jb = 0; jb < SEQ / 64; ++jb) {
        int buf = jb & 1;
        stsKV(buf);
        __syncthreads();
        if (jb + 1 < SEQ / 64) ldgKV(jb + 1);

        uint32_t kb4 = sbase + (W_K + buf * 64 * AST) * 4;
        uint32_t vb4 = sbase + (W_V + buf * 64 * AST) * 4;

        // ---- S = Q K^T ----
        float s[8][4];
        #pragma unroll
        for (int nt = 0; nt < 8; nt++)
            #pragma unroll
            for (int r = 0; r < 4; r++) s[nt][r] = 0.f;

        #pragma unroll
        for (int kcx = 0; kcx < 4; ++kcx) {
            uint32_t kcb = kcx * 32;
            #pragma unroll
            for (int p = 0; p < 4; ++p) {
                uint32_t r0, r1, r2, r3;
                LDSM4(r0, r1, r2, r3, kb4 + p * 16 * AST * 4 + boff + kcb);
                mma_f16(s[2*p],   qf[kcx][0], qf[kcx][1], qf[kcx][2], qf[kcx][3], r0, r1);
                mma_f16(s[2*p+1], qf[kcx][0], qf[kcx][1], qf[kcx][2], qf[kcx][3], r2, r3);
            }
        }

        // ---- online softmax (P stays in registers) ----
        float mc0 = s[0][0], mc1 = s[0][2];
        #pragma unroll
        for (int nt = 0; nt < 8; ++nt) {
            mc0 = fmaxf(mc0, fmaxf(s[nt][0], s[nt][1]));
            mc1 = fmaxf(mc1, fmaxf(s[nt][2], s[nt][3]));
        }
        mc0 = fmaxf(mc0, __shfl_xor_sync(0xffffffffu, mc0, 1));
        mc0 = fmaxf(mc0, __shfl_xor_sync(0xffffffffu, mc0, 2));
        mc1 = fmaxf(mc1, __shfl_xor_sync(0xffffffffu, mc1, 1));
        mc1 = fmaxf(mc1, __shfl_xor_sync(0xffffffffu, mc1, 2));
        float mn0 = fmaxf(m0, mc0), mn1 = fmaxf(m1, mc1);
        float f0 = __expf(m0 - mn0), f1 = __expf(m1 - mn1);
        m0 = mn0; m1 = mn1;

        float ps0 = 0.f, ps1 = 0.f;
        #pragma unroll
        for (int nt = 0; nt < 8; ++nt) {
            float p0 = __expf(s[nt][0] - m0);
            float p1 = __expf(s[nt][1] - m0);
            float p2 = __expf(s[nt][2] - m1);
            float p3 = __expf(s[nt][3] - m1);
            ps0 += p0 + p1; ps1 += p2 + p3;
            s[nt][0] = p0; s[nt][1] = p1; s[nt][2] = p2; s[nt][3] = p3;
        }
        ps0 += __shfl_xor_sync(0xffffffffu, ps0, 1);
        ps0 += __shfl_xor_sync(0xffffffffu, ps0, 2);
        ps1 += __shfl_xor_sync(0xffffffffu, ps1, 1);
        ps1 += __shfl_xor_sync(0xffffffffu, ps1, 2);
        l0r = l0r * f0 + ps0;
        l1r = l1r * f1 + ps1;
        #pragma unroll
        for (int nt = 0; nt < 8; ++nt) {
            oacc[nt][0] *= f0; oacc[nt][1] *= f0;
            oacc[nt][2] *= f1; oacc[nt][3] *= f1;
        }

        // ---- O += P V (register repack: C-frag == A-frag) ----
        #pragma unroll
        for (int kcx = 0; kcx < 4; ++kcx) {
            uint32_t kcb = kcx * 32;
            uint32_t pa0 = cvt2h(s[2*kcx][0],   s[2*kcx][1]);
            uint32_t pa1 = cvt2h(s[2*kcx][2],   s[2*kcx][3]);
            uint32_t pa2 = cvt2h(s[2*kcx+1][0], s[2*kcx+1][1]);
            uint32_t pa3 = cvt2h(s[2*kcx+1][2], s[2*kcx+1][3]);
            #pragma unroll
            for (int p = 0; p < 4; ++p) {
                uint32_t r0, r1, r2, r3;
                LDSM4(r0, r1, r2, r3, vb4 + p * 16 * AST * 4 + boff + kcb);
                mma_f16(oacc[2*p],   pa0, pa1, pa2, pa3, r0, r1);
                mma_f16(oacc[2*p+1], pa0, pa1, pa2, pa3, r2, r3);
            }
        }
    }

    float inv0 = 1.0f / l0r, inv1 = 1.0f / l1r;
    int grow0 = b * SEQ + qb * 128 + qrow0 + gid;
    #pragma unroll
    for (int nt = 0; nt < 8; ++nt) {
        int col = h * HD + nt * 8 + tig * 2;
        *(uint32_t*)(o + (size_t)grow0 * DIM + col) =
            cvt2h(oacc[nt][0] * inv0, oacc[nt][1] * inv0);
        *(uint32_t*)(o + (size_t)(grow0 + 8) * DIM + col) =
            cvt2h(oacc[nt][2] * inv1, oacc[nt][3] * inv1);
    }
}

// ---------------- launch ----------------
extern "C" void kernel_launch(void* const* d_in, const int* in_sizes, int n_in,
                              void* d_out, int out_size)
{
    const float* x     = (const float*)d_in[0];
    const float* qkv_w = (const float*)d_in[1];
    const float* out_w = (const float*)d_in[2];
    const float* out_b = (const float*)d_in[3];
    const float* ff_w1 = (const float*)d_in[4];
    const float* ff_b1 = (const float*)d_in[5];
    const float* ff_w2 = (const float*)d_in[6];
    const float* ff_b2 = (const float*)d_in[7];
    const float* ln1_w = (const float*)d_in[8];
    const float* ln1_b = (const float*)d_in[9];
    const float* ln2_w = (const float*)d_in[10];
    const float* ln2_b = (const float*)d_in[11];
    float* out = (float*)d_out;

    float *x1;
    __half *xln, *q, *k, *v, *attn, *xln2, *hbuf;
    __half *wq, *wo, *w1, *w2;
    cudaGetSymbolAddress((void**)&x1,   g_x1);
    cudaGetSymbolAddress((void**)&xln,  g_xln);
    cudaGetSymbolAddress((void**)&q,    g_q);
    cudaGetSymbolAddress((void**)&k,    g_k);
    cudaGetSymbolAddress((void**)&v,    g_v);
    cudaGetSymbolAddress((void**)&attn, g_attn);
    cudaGetSymbolAddress((void**)&xln2, g_xln2);
    cudaGetSymbolAddress((void**)&hbuf, g_h);
    cudaGetSymbolAddress((void**)&wq,   g_wqkv);
    cudaGetSymbolAddress((void**)&wo,   g_wout);
    cudaGetSymbolAddress((void**)&w1,   g_w1);
    cudaGetSymbolAddress((void**)&w2,   g_w2);

    cudaFuncSetAttribute(gemm_f16<EPI_QKV>,
        cudaFuncAttributeMaxDynamicSharedMemorySize, GEMM_SMEM);
    cudaFuncSetAttribute(gemm_f16<EPI_BIAS_RES>,
        cudaFuncAttributeMaxDynamicSharedMemorySize, GEMM_SMEM);
    cudaFuncSetAttribute(gemm_f16<EPI_SILU_H>,
        cudaFuncAttributeMaxDynamicSharedMemorySize, GEMM_SMEM);
    cudaFuncSetAttribute(attn_f16,
        cudaFuncAttributeMaxDynamicSharedMemorySize, ATTN_SM_BYTES);

    // 0. convert all weights to fp16 (single launch)
    conv_all<<<(CB3 + 1023) / 1024, 256>>>(qkv_w, out_w, ff_w1, ff_w2, wq, wo, w1, w2);

    // 1. LN1 -> fp16
    ln_kernel<<<TOK / 8, 256>>>(x, ln1_w, ln1_b, xln);
    // 2. QKV -> fp16 q(scaled)/k/v
    gemm_f16<EPI_QKV><<<dim3(3 * DIM / 128, TOK / 128), 256, GEMM_SMEM>>>(
        xln, wq, nullptr, nullptr, nullptr, q, k, v, TOK, 3 * DIM, DIM);
    // 3. attention -> fp16
    attn_f16<<<dim3(SEQ / 128, 2 * NHEAD), 256, ATTN_SM_BYTES>>>(q, k, v, attn);
    // 4. x1 = x + attn @ out_w^T + out_b -> fp32
    gemm_f16<EPI_BIAS_RES><<<dim3(DIM / 128, TOK / 128), 256, GEMM_SMEM>>>(
        attn, wo, out_b, x, x1, nullptr, nullptr, nullptr, TOK, DIM, DIM);
    // 5. LN2 -> fp16
    ln_kernel<<<TOK / 8, 256>>>(x1, ln2_w, ln2_b, xln2);
    // 6. h = silu(...) -> fp16
    gemm_f16<EPI_SILU_H><<<dim3(MLPD / 128, TOK / 128), 256, GEMM_SMEM>>>(
        xln2, w1, ff_b1, nullptr, nullptr, hbuf, nullptr, nullptr, TOK, MLPD, DIM);
    // 7. out = x1 + h @ ff_w2^T + ff_b2 -> fp32
    gemm_f16<EPI_BIAS_RES><<<dim3(DIM / 128, TOK / 128), 256, GEMM_SMEM>>>(
        hbuf, w2, ff_b2, x1, out, nullptr, nullptr, nullptr, TOK, DIM, MLPD);
}

// round 14
// speedup vs baseline: 1.0753x; 1.0753x over previous
#include <cuda_runtime.h>
#include <cuda_fp16.h>
#include <math.h>
#include <stdint.h>

#define TOK   4096
#define DIM   1024
#define MLPD  4096
#define NHEAD 16
#define HD    64
#define SEQ   2048

// ---------------- scratch ----------------
__device__ float g_x1  [TOK * DIM];
__device__ __half g_xln [TOK * DIM];
__device__ __half g_q   [TOK * DIM];   // Q (scaled)
__device__ __half g_k   [TOK * DIM];   // K
__device__ __half g_v   [TOK * DIM];   // V
__device__ __half g_attn[TOK * DIM];
__device__ __half g_xln2[TOK * DIM];
__device__ __half g_h   [TOK * MLPD];
__device__ __half g_wqkv[3 * DIM * DIM];
__device__ __half g_wout[DIM * DIM];
__device__ __half g_w1  [MLPD * DIM];
__device__ __half g_w2  [DIM * MLPD];

// ---------------- helpers ----------------
__device__ __forceinline__ uint32_t cvt2h(float x, float y) {
    __half2 h = __floats2half2_rn(x, y);
    return *(uint32_t*)&h;
}

__device__ __forceinline__ void mma_f16(float* d,
    uint32_t a0, uint32_t a1, uint32_t a2, uint32_t a3,
    uint32_t b0, uint32_t b1)
{
    asm volatile(
        "mma.sync.aligned.m16n8k16.row.col.f32.f16.f16.f32 "
        "{%0,%1,%2,%3}, {%4,%5,%6,%7}, {%8,%9}, {%0,%1,%2,%3};"
        : "+f"(d[0]), "+f"(d[1]), "+f"(d[2]), "+f"(d[3])
        : "r"(a0), "r"(a1), "r"(a2), "r"(a3), "r"(b0), "r"(b1));
}

#define LDSM4(R0,R1,R2,R3,ADDR) \
    asm volatile("ldmatrix.sync.aligned.m8n8.x4.shared.b16 {%0,%1,%2,%3}, [%4];" \
        : "=r"(R0), "=r"(R1), "=r"(R2), "=r"(R3) : "r"(ADDR))

#define CP16(dst, src) \
    asm volatile("cp.async.ca.shared.global [%0], [%1], 16;" :: "r"(dst), "l"(src) : "memory")
#define CP_COMMIT() asm volatile("cp.async.commit_group;" ::: "memory")
#define CP_WAIT2()  asm volatile("cp.async.wait_group 2;" ::: "memory")

// ---------------- merged weight convert (fp32 -> fp16) ----------------
#define CB0 (3 * DIM * DIM / 4)
#define CB1 (CB0 + DIM * DIM / 4)
#define CB2 (CB1 + MLPD * DIM / 4)
#define CB3 (CB2 + DIM * MLPD / 4)

__global__ __launch_bounds__(256) void conv_all(
    const float* __restrict__ s0, const float* __restrict__ s1,
    const float* __restrict__ s2, const float* __restrict__ s3,
    __half* __restrict__ d0, __half* __restrict__ d1,
    __half* __restrict__ d2, __half* __restrict__ d3)
{
    int i0 = blockIdx.x * 1024 + threadIdx.x;
    #pragma unroll
    for (int k2 = 0; k2 < 4; ++k2) {
        int i = i0 + k2 * 256;
        if (i < CB3) {
            const float* sp; __half* dp; int off;
            if (i < CB0)      { sp = s0; dp = d0; off = i; }
            else if (i < CB1) { sp = s1; dp = d1; off = i - CB0; }
            else if (i < CB2) { sp = s2; dp = d2; off = i - CB1; }
            else              { sp = s3; dp = d3; off = i - CB2; }
            float4 v = ((const float4*)sp)[off];
            ((uint2*)dp)[off] = make_uint2(cvt2h(v.x, v.y), cvt2h(v.z, v.w));
        }
    }
}

// ---------------- LayerNorm, warp-per-row ----------------
__global__ __launch_bounds__(256) void ln_kernel(
    const float* __restrict__ x, const float* __restrict__ w,
    const float* __restrict__ b, __half* __restrict__ o)
{
    int warp = threadIdx.x >> 5, lane = threadIdx.x & 31;
    int row = blockIdx.x * 8 + warp;
    const float4* xr = (const float4*)(x + (size_t)row * DIM);
    float4 v[8];
    float s = 0.f, sq = 0.f;
    #pragma unroll
    for (int i = 0; i < 8; i++) {
        v[i] = xr[lane + i * 32];
        s  += v[i].x + v[i].y + v[i].z + v[i].w;
        sq += v[i].x*v[i].x + v[i].y*v[i].y + v[i].z*v[i].z + v[i].w*v[i].w;
    }
    #pragma unroll
    for (int of = 16; of > 0; of >>= 1) {
        s  += __shfl_xor_sync(0xffffffffu, s,  of);
        sq += __shfl_xor_sync(0xffffffffu, sq, of);
    }
    float mean = s * (1.0f / DIM);
    float rstd = rsqrtf(sq * (1.0f / DIM) - mean * mean + 1e-5f);
    uint2* orow = (uint2*)o + (size_t)row * (DIM / 4);
    #pragma unroll
    for (int i = 0; i < 8; i++) {
        int idx = lane + i * 32;
        float4 wv = ((const float4*)w)[idx];
        float4 bv = ((const float4*)b)[idx];
        float ox = (v[i].x - mean) * rstd * wv.x + bv.x;
        float oy = (v[i].y - mean) * rstd * wv.y + bv.y;
        float oz = (v[i].z - mean) * rstd * wv.z + bv.z;
        float ow = (v[i].w - mean) * rstd * wv.w + bv.w;
        orow[idx] = make_uint2(cvt2h(ox, oy), cvt2h(oz, ow));
    }
}

// ---------------- NT GEMM fp16, KT=32, 4-stage cp.async, ldmatrix ----------
#define EPI_NONE      0
#define EPI_BIAS_RES  1
#define EPI_SILU_H    2
#define EPI_QKV       3

#define WST2 20
#define PLW2 (128 * WST2)
#define STGW2 (2 * PLW2)
#define NSTAGE 4
#define GEMM_SMEM (NSTAGE * STGW2 * 4)   // 81920

template <int EPI>
__global__ __launch_bounds__(256, 2) void gemm_f16(
    const __half* __restrict__ A, const __half* __restrict__ W,
    const float* __restrict__ bias, const float* __restrict__ res,
    float* __restrict__ C,
    __half* __restrict__ H0, __half* __restrict__ H1, __half* __restrict__ H2,
    int M, int N, int K)
{
    extern __shared__ __align__(16) uint32_t smw[];
    uint32_t sbase = (uint32_t)__cvta_generic_to_shared(smw);

    int tid  = threadIdx.x;
    int warp = tid >> 5, lane = tid & 31;
    int bm   = blockIdx.y * 128;
    int bn   = blockIdx.x * 128;
    int wm   = (warp & 1) * 64;
    int wn   = (warp >> 1) * 32;
    int gid  = lane >> 2, tig = lane & 3;

    int lrow  = tid >> 1;
    int lh    = tid & 1;
    const __half* pA = A + (size_t)(bm + lrow) * K + lh * 16;
    const __half* pW = W + (size_t)(bn + lrow) * K + lh * 16;
    uint32_t dstb = (uint32_t)(lrow * WST2 + lh * 8) * 4;

    uint32_t a_off = (uint32_t)(((wm + (lane & 15)) * WST2 + (lane >> 4) * 4) * 4);
    uint32_t b_off = (uint32_t)(((wn + ((lane >> 4) & 1) * 8 + (lane & 7)) * WST2
                                 + ((lane >> 3) & 1) * 4) * 4);

    float acc[4][4][4];
    #pragma unroll
    for (int i = 0; i < 4; i++)
        #pragma unroll
        for (int j = 0; j < 4; j++)
            #pragma unroll
            for (int r = 0; r < 4; r++) acc[i][j][r] = 0.f;

    int ntiles = K >> 5;

    auto issue = [&](int t) {
        uint32_t base = sbase + ((t % NSTAGE) * STGW2) * 4 + dstb;
        const __half* a = pA + (size_t)t * 32;
        const __half* w = pW + (size_t)t * 32;
        CP16(base,               a);
        CP16(base + 16,          a + 8);
        CP16(base + PLW2*4,      w);
        CP16(base + PLW2*4 + 16, w + 8);
    };

    issue(0); CP_COMMIT();
    issue(1); CP_COMMIT();
    issue(2); CP_COMMIT();

    for (int t = 0; t < ntiles; ++t) {
        CP_WAIT2();
        __syncthreads();
        uint32_t stb = sbase + ((t % NSTAGE) * STGW2) * 4;

        #pragma unroll
        for (int kc = 0; kc < 2; ++kc) {
            uint32_t kcb = kc * 32;
            uint32_t bw[4][2];
            #pragma unroll
            for (int p = 0; p < 2; ++p) {
                uint32_t r0, r1, r2, r3;
                LDSM4(r0, r1, r2, r3, stb + PLW2*4 + b_off + p * 16 * WST2 * 4 + kcb);
                bw[2*p][0] = r0; bw[2*p][1] = r1; bw[2*p+1][0] = r2; bw[2*p+1][1] = r3;
            }
            #pragma unroll
            for (int mt = 0; mt < 4; ++mt) {
                uint32_t a0, a1, a2, a3;
                LDSM4(a0, a1, a2, a3, stb + a_off + mt * 16 * WST2 * 4 + kcb);
                #pragma unroll
                for (int nt = 0; nt < 4; ++nt)
                    mma_f16(acc[mt][nt], a0, a1, a2, a3, bw[nt][0], bw[nt][1]);
            }
        }
        if (t + 3 < ntiles) issue(t + 3);
        CP_COMMIT();
    }

    // ---- epilogue ----
    #pragma unroll
    for (int mt = 0; mt < 4; ++mt) {
        #pragma unroll
        for (int nt = 0; nt < 4; ++nt) {
            int row = bm + wm + mt * 16 + gid;
            int col = bn + wn + nt * 8 + tig * 2;
            float2 v0 = make_float2(acc[mt][nt][0], acc[mt][nt][1]);
            float2 v1 = make_float2(acc[mt][nt][2], acc[mt][nt][3]);
            if (EPI == EPI_BIAS_RES || EPI == EPI_SILU_H) {
                float bx = bias[col], by = bias[col + 1];
                v0.x += bx; v0.y += by; v1.x += bx; v1.y += by;
            }
            if (EPI == EPI_BIAS_RES) {
                float2 r0 = *(const float2*)(res + (size_t)row * N + col);
                float2 r1 = *(const float2*)(res + (size_t)(row + 8) * N + col);
                v0.x += r0.x; v0.y += r0.y; v1.x += r1.x; v1.y += r1.y;
                *(float2*)(C + (size_t)row * N + col)       = v0;
                *(float2*)(C + (size_t)(row + 8) * N + col) = v1;
            } else if (EPI == EPI_SILU_H) {
                v0.x *= 1.f / (1.f + __expf(-v0.x));
                v0.y *= 1.f / (1.f + __expf(-v0.y));
                v1.x *= 1.f / (1.f + __expf(-v1.x));
                v1.y *= 1.f / (1.f + __expf(-v1.y));
                *(uint32_t*)(H0 + (size_t)row * N + col)       = cvt2h(v0.x, v0.y);
                *(uint32_t*)(H0 + (size_t)(row + 8) * N + col) = cvt2h(v1.x, v1.y);
            } else if (EPI == EPI_QKV) {
                int region = col >> 10;
                int colr   = col & 1023;
                __half* dst = (region == 0) ? H0 : (region == 1) ? H1 : H2;
                float sc = (region == 0) ? 0.125f : 1.0f;
                *(uint32_t*)(dst + (size_t)row * DIM + colr) =
                    cvt2h(v0.x * sc, v0.y * sc);
                *(uint32_t*)(dst + (size_t)(row + 8) * DIM + colr) =
                    cvt2h(v1.x * sc, v1.y * sc);
            } else {
                *(float2*)(C + (size_t)row * N + col)       = v0;
                *(float2*)(C + (size_t)(row + 8) * N + col) = v1;
            }
        }
    }
}

// ---------------- Flash attention fp16, K/V register-prefetch pipeline -----
#define AST 36
#define W_Q 0
#define W_K (W_Q + 128 * AST)                 // double-buffered: 2 x 64 rows
#define W_V (W_K + 2 * 64 * AST)
#define ATTN_WORDS (W_V + 2 * 64 * AST)
#define ATTN_SM_BYTES (ATTN_WORDS * 4)        // 55296

__global__ __launch_bounds__(256, 2) void attn_f16(
    const __half* __restrict__ Qg, const __half* __restrict__ Kg,
    const __half* __restrict__ Vg, __half* __restrict__ o)
{
    extern __shared__ uint32_t smw[];
    uint32_t sbase = (uint32_t)__cvta_generic_to_shared(smw);
    uint32_t* Qs = smw + W_Q;
    uint32_t* Kb = smw + W_K;
    uint32_t* Vb = smw + W_V;

    int tid  = threadIdx.x;
    int warp = tid >> 5, lane = tid & 31;
    int gid  = lane >> 2, tig = lane & 3;
    int qrow0 = warp * 16;

    int qb = blockIdx.x;
    int b  = blockIdx.y >> 4;
    int h  = blockIdx.y & 15;

    uint32_t aoff = (uint32_t)((((lane & 15)) * AST + (lane >> 4) * 4) * 4);
    uint32_t boff = (uint32_t)(((((lane >> 4) & 1) * 8 + (lane & 7)) * AST
                                + ((lane >> 3) & 1) * 4) * 4);

    int kr = tid >> 3, kc = (tid & 7) * 8;
    int vr = tid >> 4, vc = (tid & 15) * 4;

    const __half* kbase = Kg + (size_t)(b * SEQ) * DIM + h * HD;
    const __half* vbase = Vg + (size_t)(b * SEQ) * DIM + h * HD;

    uint4 kA, kB;
    uint2 vA0, vA1, vB0, vB1;
    auto ldgKV = [&](int jb) {
        const __half* kg = kbase + (size_t)(jb * 64) * DIM;
        const __half* vg = vbase + (size_t)(jb * 64) * DIM;
        kA = *(const uint4*)(kg + (size_t)kr * DIM + kc);
        kB = *(const uint4*)(kg + (size_t)(kr + 32) * DIM + kc);
        vA0 = *(const uint2*)(vg + (size_t)(2 * vr) * DIM + vc);
        vA1 = *(const uint2*)(vg + (size_t)(2 * vr + 1) * DIM + vc);
        vB0 = *(const uint2*)(vg + (size_t)(2 * (vr + 16)) * DIM + vc);
        vB1 = *(const uint2*)(vg + (size_t)(2 * (vr + 16) + 1) * DIM + vc);
    };
    auto stsKV = [&](int buf) {
        uint32_t* kp = Kb + buf * 64 * AST;
        *(uint4*)(kp + kr * AST + (kc >> 1))        = kA;
        *(uint4*)(kp + (kr + 32) * AST + (kc >> 1)) = kB;
        uint32_t* vp = Vb + buf * 64 * AST;
        vp[(vc + 0) * AST + vr] = __byte_perm(vA0.x, vA1.x, 0x5410);
        vp[(vc + 1) * AST + vr] = __byte_perm(vA0.x, vA1.x, 0x7632);
        vp[(vc + 2) * AST + vr] = __byte_perm(vA0.y, vA1.y, 0x5410);
        vp[(vc + 3) * AST + vr] = __byte_perm(vA0.y, vA1.y, 0x7632);
        vp[(vc + 0) * AST + vr + 16] = __byte_perm(vB0.x, vB1.x, 0x5410);
        vp[(vc + 1) * AST + vr + 16] = __byte_perm(vB0.x, vB1.x, 0x7632);
        vp[(vc + 2) * AST + vr + 16] = __byte_perm(vB0.y, vB1.y, 0x5410);
        vp[(vc + 3) * AST + vr + 16] = __byte_perm(vB0.y, vB1.y, 0x7632);
    };

    // prologue: start K/V(0) loads, fill Q
    ldgKV(0);
    {
        const __half* qg = Qg + (size_t)(b * SEQ + qb * 128) * DIM + h * HD;
        for (int e = tid; e < 128 * 8; e += 256) {
            int r = e >> 3, c = (e & 7) * 8;
            uint4 v = *(const uint4*)(qg + (size_t)r * DIM + c);
            *(uint4*)(Qs + r * AST + (c >> 1)) = v;
        }
    }

    float m0 = -1e30f, m1 = -1e30f, l0r = 0.f, l1r = 0.f;
    float oacc[8][4];
    #pragma unroll
    for (int nt = 0; nt < 8; nt++)
        #pragma unroll
        for (int r = 0; r < 4; r++) oacc[nt][r] = 0.f;

    for (int jb = 0; jb < SEQ / 64; ++jb) {
        int buf = jb & 1;
        stsKV(buf);
        __syncthreads();
        if (jb + 1 < SEQ / 64) ldgKV(jb + 1);

        uint32_t kb4 = sbase + (W_K + buf * 64 * AST) * 4;
        uint32_t vb4 = sbase + (W_V + buf * 64 * AST) * 4;

        // ---- S = Q K^T ----
        float s[8][4];
        #pragma unroll
        for (int nt = 0; nt < 8; nt++)
            #pragma unroll
            for (int r = 0; r < 4; r++) s[nt][r] = 0.f;

        #pragma unroll
        for (int kcx = 0; kcx < 4; ++kcx) {
            uint32_t kcb = kcx * 32;
            uint32_t qa0, qa1, qa2, qa3;
            LDSM4(qa0, qa1, qa2, qa3, sbase + (W_Q + qrow0 * AST) * 4 + aoff + kcb);
            #pragma unroll
            for (int p = 0; p < 4; ++p) {
                uint32_t r0, r1, r2, r3;
                LDSM4(r0, r1, r2, r3, kb4 + p * 16 * AST * 4 + boff + kcb);
                mma_f16(s[2*p],   qa0, qa1, qa2, qa3, r0, r1);
                mma_f16(s[2*p+1], qa0, qa1, qa2, qa3, r2, r3);
            }
        }

        // ---- online softmax (P stays in registers) ----
        float mc0 = s[0][0], mc1 = s[0][2];
        #pragma unroll
        for (int nt = 0; nt < 8; ++nt) {
            mc0 = fmaxf(mc0, fmaxf(s[nt][0], s[nt][1]));
            mc1 = fmaxf(mc1, fmaxf(s[nt][2], s[nt][3]));
        }
        mc0 = fmaxf(mc0, __shfl_xor_sync(0xffffffffu, mc0, 1));
        mc0 = fmaxf(mc0, __shfl_xor_sync(0xffffffffu, mc0, 2));
        mc1 = fmaxf(mc1, __shfl_xor_sync(0xffffffffu, mc1, 1));
        mc1 = fmaxf(mc1, __shfl_xor_sync(0xffffffffu, mc1, 2));
        float mn0 = fmaxf(m0, mc0), mn1 = fmaxf(m1, mc1);
        float f0 = __expf(m0 - mn0), f1 = __expf(m1 - mn1);
        m0 = mn0; m1 = mn1;

        float ps0 = 0.f, ps1 = 0.f;
        #pragma unroll
        for (int nt = 0; nt < 8; ++nt) {
            float p0 = __expf(s[nt][0] - m0);
            float p1 = __expf(s[nt][1] - m0);
            float p2 = __expf(s[nt][2] - m1);
            float p3 = __expf(s[nt][3] - m1);
            ps0 += p0 + p1; ps1 += p2 + p3;
            s[nt][0] = p0; s[nt][1] = p1; s[nt][2] = p2; s[nt][3] = p3;
        }
        ps0 += __shfl_xor_sync(0xffffffffu, ps0, 1);
        ps0 += __shfl_xor_sync(0xffffffffu, ps0, 2);
        ps1 += __shfl_xor_sync(0xffffffffu, ps1, 1);
        ps1 += __shfl_xor_sync(0xffffffffu, ps1, 2);
        l0r = l0r * f0 + ps0;
        l1r = l1r * f1 + ps1;
        // rescale O only if any row's max actually moved (warp-uniform branch)
        bool need = (f0 != 1.0f) || (f1 != 1.0f);
        if (__any_sync(0xffffffffu, need)) {
            #pragma unroll
            for (int nt = 0; nt < 8; ++nt) {
                oacc[nt][0] *= f0; oacc[nt][1] *= f0;
                oacc[nt][2] *= f1; oacc[nt][3] *= f1;
            }
        }

        // ---- O += P V (register repack: C-frag == A-frag) ----
        #pragma unroll
        for (int kcx = 0; kcx < 4; ++kcx) {
            uint32_t kcb = kcx * 32;
            uint32_t pa0 = cvt2h(s[2*kcx][0],   s[2*kcx][1]);
            uint32_t pa1 = cvt2h(s[2*kcx][2],   s[2*kcx][3]);
            uint32_t pa2 = cvt2h(s[2*kcx+1][0], s[2*kcx+1][1]);
            uint32_t pa3 = cvt2h(s[2*kcx+1][2], s[2*kcx+1][3]);
            #pragma unroll
            for (int p = 0; p < 4; ++p) {
                uint32_t r0, r1, r2, r3;
                LDSM4(r0, r1, r2, r3, vb4 + p * 16 * AST * 4 + boff + kcb);
                mma_f16(oacc[2*p],   pa0, pa1, pa2, pa3, r0, r1);
                mma_f16(oacc[2*p+1], pa0, pa1, pa2, pa3, r2, r3);
            }
        }
    }

    float inv0 = 1.0f / l0r, inv1 = 1.0f / l1r;
    int grow0 = b * SEQ + qb * 128 + qrow0 + gid;
    #pragma unroll
    for (int nt = 0; nt < 8; ++nt) {
        int col = h * HD + nt * 8 + tig * 2;
        *(uint32_t*)(o + (size_t)grow0 * DIM + col) =
            cvt2h(oacc[nt][0] * inv0, oacc[nt][1] * inv0);
        *(uint32_t*)(o + (size_t)(grow0 + 8) * DIM + col) =
            cvt2h(oacc[nt][2] * inv1, oacc[nt][3] * inv1);
    }
}

// ---------------- launch ----------------
extern "C" void kernel_launch(void* const* d_in, const int* in_sizes, int n_in,
                              void* d_out, int out_size)
{
    const float* x     = (const float*)d_in[0];
    const float* qkv_w = (const float*)d_in[1];
    const float* out_w = (const float*)d_in[2];
    const float* out_b = (const float*)d_in[3];
    const float* ff_w1 = (const float*)d_in[4];
    const float* ff_b1 = (const float*)d_in[5];
    const float* ff_w2 = (const float*)d_in[6];
    const float* ff_b2 = (const float*)d_in[7];
    const float* ln1_w = (const float*)d_in[8];
    const float* ln1_b = (const float*)d_in[9];
    const float* ln2_w = (const float*)d_in[10];
    const float* ln2_b = (const float*)d_in[11];
    float* out = (float*)d_out;

    float *x1;
    __half *xln, *q, *k, *v, *attn, *xln2, *hbuf;
    __half *wq, *wo, *w1, *w2;
    cudaGetSymbolAddress((void**)&x1,   g_x1);
    cudaGetSymbolAddress((void**)&xln,  g_xln);
    cudaGetSymbolAddress((void**)&q,    g_q);
    cudaGetSymbolAddress((void**)&k,    g_k);
    cudaGetSymbolAddress((void**)&v,    g_v);
    cudaGetSymbolAddress((void**)&attn, g_attn);
    cudaGetSymbolAddress((void**)&xln2, g_xln2);
    cudaGetSymbolAddress((void**)&hbuf, g_h);
    cudaGetSymbolAddress((void**)&wq,   g_wqkv);
    cudaGetSymbolAddress((void**)&wo,   g_wout);
    cudaGetSymbolAddress((void**)&w1,   g_w1);
    cudaGetSymbolAddress((void**)&w2,   g_w2);

    cudaFuncSetAttribute(gemm_f16<EPI_QKV>,
        cudaFuncAttributeMaxDynamicSharedMemorySize, GEMM_SMEM);
    cudaFuncSetAttribute(gemm_f16<EPI_BIAS_RES>,
        cudaFuncAttributeMaxDynamicSharedMemorySize, GEMM_SMEM);
    cudaFuncSetAttribute(gemm_f16<EPI_SILU_H>,
        cudaFuncAttributeMaxDynamicSharedMemorySize, GEMM_SMEM);
    cudaFuncSetAttribute(attn_f16,
        cudaFuncAttributeMaxDynamicSharedMemorySize, ATTN_SM_BYTES);

    // 0. convert all weights to fp16 (single launch)
    conv_all<<<(CB3 + 1023) / 1024, 256>>>(qkv_w, out_w, ff_w1, ff_w2, wq, wo, w1, w2);

    // 1. LN1 -> fp16
    ln_kernel<<<TOK / 8, 256>>>(x, ln1_w, ln1_b, xln);
    // 2. QKV -> fp16 q(scaled)/k/v
    gemm_f16<EPI_QKV><<<dim3(3 * DIM / 128, TOK / 128), 256, GEMM_SMEM>>>(
        xln, wq, nullptr, nullptr, nullptr, q, k, v, TOK, 3 * DIM, DIM);
    // 3. attention -> fp16
    attn_f16<<<dim3(SEQ / 128, 2 * NHEAD), 256, ATTN_SM_BYTES>>>(q, k, v, attn);
    // 4. x1 = x + attn @ out_w^T + out_b -> fp32
    gemm_f16<EPI_BIAS_RES><<<dim3(DIM / 128, TOK / 128), 256, GEMM_SMEM>>>(
        attn, wo, out_b, x, x1, nullptr, nullptr, nullptr, TOK, DIM, DIM);
    // 5. LN2 -> fp16
    ln_kernel<<<TOK / 8, 256>>>(x1, ln2_w, ln2_b, xln2);
    // 6. h = silu(...) -> fp16
    gemm_f16<EPI_SILU_H><<<dim3(MLPD / 128, TOK / 128), 256, GEMM_SMEM>>>(
        xln2, w1, ff_b1, nullptr, nullptr, hbuf, nullptr, nullptr, TOK, MLPD, DIM);
    // 7. out = x1 + h @ ff_w2^T + ff_b2 -> fp32
    gemm_f16<EPI_BIAS_RES><<<dim3(DIM / 128, TOK / 128), 256, GEMM_SMEM>>>(
        hbuf, w2, ff_b2, x1, out, nullptr, nullptr, nullptr, TOK, DIM, MLPD);
}

// round 15
// speedup vs baseline: 1.1078x; 1.0302x over previous
#include <cuda_runtime.h>
#include <cuda_fp16.h>
#include <math.h>
#include <stdint.h>

#define TOK   4096
#define DIM   1024
#define MLPD  4096
#define NHEAD 16
#define HD    64
#define SEQ   2048

// ---------------- scratch ----------------
__device__ float g_x1  [TOK * DIM];
__device__ __half g_xln [TOK * DIM];
__device__ __half g_q   [TOK * DIM];   // Q (scaled)
__device__ __half g_k   [TOK * DIM];   // K
__device__ __half g_v   [TOK * DIM];   // V
__device__ __half g_attn[TOK * DIM];
__device__ __half g_xln2[TOK * DIM];
__device__ __half g_h   [TOK * MLPD];
__device__ __half g_wqkv[3 * DIM * DIM];
__device__ __half g_wout[DIM * DIM];
__device__ __half g_w1  [MLPD * DIM];
__device__ __half g_w2  [DIM * MLPD];

// ---------------- helpers ----------------
__device__ __forceinline__ uint32_t cvt2h(float x, float y) {
    __half2 h = __floats2half2_rn(x, y);
    return *(uint32_t*)&h;
}

__device__ __forceinline__ void mma_f16(float* d,
    uint32_t a0, uint32_t a1, uint32_t a2, uint32_t a3,
    uint32_t b0, uint32_t b1)
{
    asm volatile(
        "mma.sync.aligned.m16n8k16.row.col.f32.f16.f16.f32 "
        "{%0,%1,%2,%3}, {%4,%5,%6,%7}, {%8,%9}, {%0,%1,%2,%3};"
        : "+f"(d[0]), "+f"(d[1]), "+f"(d[2]), "+f"(d[3])
        : "r"(a0), "r"(a1), "r"(a2), "r"(a3), "r"(b0), "r"(b1));
}

#define LDSM4(R0,R1,R2,R3,ADDR) \
    asm volatile("ldmatrix.sync.aligned.m8n8.x4.shared.b16 {%0,%1,%2,%3}, [%4];" \
        : "=r"(R0), "=r"(R1), "=r"(R2), "=r"(R3) : "r"(ADDR))
#define LDSM4T(R0,R1,R2,R3,ADDR) \
    asm volatile("ldmatrix.sync.aligned.m8n8.x4.trans.shared.b16 {%0,%1,%2,%3}, [%4];" \
        : "=r"(R0), "=r"(R1), "=r"(R2), "=r"(R3) : "r"(ADDR))

#define CP16(dst, src) \
    asm volatile("cp.async.ca.shared.global [%0], [%1], 16;" :: "r"(dst), "l"(src) : "memory")
#define CP_COMMIT() asm volatile("cp.async.commit_group;" ::: "memory")
#define CP_WAIT2()  asm volatile("cp.async.wait_group 2;" ::: "memory")
#define CP_WAIT1()  asm volatile("cp.async.wait_group 1;" ::: "memory")

// ---------------- merged weight convert (fp32 -> fp16) ----------------
#define CB0 (3 * DIM * DIM / 4)
#define CB1 (CB0 + DIM * DIM / 4)
#define CB2 (CB1 + MLPD * DIM / 4)
#define CB3 (CB2 + DIM * MLPD / 4)

__global__ __launch_bounds__(256) void conv_all(
    const float* __restrict__ s0, const float* __restrict__ s1,
    const float* __restrict__ s2, const float* __restrict__ s3,
    __half* __restrict__ d0, __half* __restrict__ d1,
    __half* __restrict__ d2, __half* __restrict__ d3)
{
    int i0 = blockIdx.x * 1024 + threadIdx.x;
    #pragma unroll
    for (int k2 = 0; k2 < 4; ++k2) {
        int i = i0 + k2 * 256;
        if (i < CB3) {
            const float* sp; __half* dp; int off;
            if (i < CB0)      { sp = s0; dp = d0; off = i; }
            else if (i < CB1) { sp = s1; dp = d1; off = i - CB0; }
            else if (i < CB2) { sp = s2; dp = d2; off = i - CB1; }
            else              { sp = s3; dp = d3; off = i - CB2; }
            float4 v = ((const float4*)sp)[off];
            ((uint2*)dp)[off] = make_uint2(cvt2h(v.x, v.y), cvt2h(v.z, v.w));
        }
    }
}

// ---------------- LayerNorm, warp-per-row ----------------
__global__ __launch_bounds__(256) void ln_kernel(
    const float* __restrict__ x, const float* __restrict__ w,
    const float* __restrict__ b, __half* __restrict__ o)
{
    int warp = threadIdx.x >> 5, lane = threadIdx.x & 31;
    int row = blockIdx.x * 8 + warp;
    const float4* xr = (const float4*)(x + (size_t)row * DIM);
    float4 v[8];
    float s = 0.f, sq = 0.f;
    #pragma unroll
    for (int i = 0; i < 8; i++) {
        v[i] = xr[lane + i * 32];
        s  += v[i].x + v[i].y + v[i].z + v[i].w;
        sq += v[i].x*v[i].x + v[i].y*v[i].y + v[i].z*v[i].z + v[i].w*v[i].w;
    }
    #pragma unroll
    for (int of = 16; of > 0; of >>= 1) {
        s  += __shfl_xor_sync(0xffffffffu, s,  of);
        sq += __shfl_xor_sync(0xffffffffu, sq, of);
    }
    float mean = s * (1.0f / DIM);
    float rstd = rsqrtf(sq * (1.0f / DIM) - mean * mean + 1e-5f);
    uint2* orow = (uint2*)o + (size_t)row * (DIM / 4);
    #pragma unroll
    for (int i = 0; i < 8; i++) {
        int idx = lane + i * 32;
        float4 wv = ((const float4*)w)[idx];
        float4 bv = ((const float4*)b)[idx];
        float ox = (v[i].x - mean) * rstd * wv.x + bv.x;
        float oy = (v[i].y - mean) * rstd * wv.y + bv.y;
        float oz = (v[i].z - mean) * rstd * wv.z + bv.z;
        float ow = (v[i].w - mean) * rstd * wv.w + bv.w;
        orow[idx] = make_uint2(cvt2h(ox, oy), cvt2h(oz, ow));
    }
}

// ---------------- NT GEMM fp16, KT=32, 4-stage cp.async, ldmatrix ----------
#define EPI_NONE      0
#define EPI_BIAS_RES  1
#define EPI_SILU_H    2
#define EPI_QKV       3

#define WST2 20
#define PLW2 (128 * WST2)
#define STGW2 (2 * PLW2)
#define NSTAGE 4
#define GEMM_SMEM (NSTAGE * STGW2 * 4)   // 81920

template <int EPI>
__global__ __launch_bounds__(256, 2) void gemm_f16(
    const __half* __restrict__ A, const __half* __restrict__ W,
    const float* __restrict__ bias, const float* __restrict__ res,
    float* __restrict__ C,
    __half* __restrict__ H0, __half* __restrict__ H1, __half* __restrict__ H2,
    int M, int N, int K)
{
    extern __shared__ __align__(16) uint32_t smw[];
    uint32_t sbase = (uint32_t)__cvta_generic_to_shared(smw);

    int tid  = threadIdx.x;
    int warp = tid >> 5, lane = tid & 31;
    int bm   = blockIdx.y * 128;
    int bn   = blockIdx.x * 128;
    int wm   = (warp & 1) * 64;
    int wn   = (warp >> 1) * 32;
    int gid  = lane >> 2, tig = lane & 3;

    int lrow  = tid >> 1;
    int lh    = tid & 1;
    const __half* pA = A + (size_t)(bm + lrow) * K + lh * 16;
    const __half* pW = W + (size_t)(bn + lrow) * K + lh * 16;
    uint32_t dstb = (uint32_t)(lrow * WST2 + lh * 8) * 4;

    uint32_t a_off = (uint32_t)(((wm + (lane & 15)) * WST2 + (lane >> 4) * 4) * 4);
    uint32_t b_off = (uint32_t)(((wn + ((lane >> 4) & 1) * 8 + (lane & 7)) * WST2
                                 + ((lane >> 3) & 1) * 4) * 4);

    float acc[4][4][4];
    #pragma unroll
    for (int i = 0; i < 4; i++)
        #pragma unroll
        for (int j = 0; j < 4; j++)
            #pragma unroll
            for (int r = 0; r < 4; r++) acc[i][j][r] = 0.f;

    int ntiles = K >> 5;

    auto issue = [&](int t) {
        uint32_t base = sbase + ((t % NSTAGE) * STGW2) * 4 + dstb;
        const __half* a = pA + (size_t)t * 32;
        const __half* w = pW + (size_t)t * 32;
        CP16(base,               a);
        CP16(base + 16,          a + 8);
        CP16(base + PLW2*4,      w);
        CP16(base + PLW2*4 + 16, w + 8);
    };

    issue(0); CP_COMMIT();
    issue(1); CP_COMMIT();
    issue(2); CP_COMMIT();

    for (int t = 0; t < ntiles; ++t) {
        CP_WAIT2();
        __syncthreads();
        uint32_t stb = sbase + ((t % NSTAGE) * STGW2) * 4;

        #pragma unroll
        for (int kc = 0; kc < 2; ++kc) {
            uint32_t kcb = kc * 32;
            uint32_t bw[4][2];
            #pragma unroll
            for (int p = 0; p < 2; ++p) {
                uint32_t r0, r1, r2, r3;
                LDSM4(r0, r1, r2, r3, stb + PLW2*4 + b_off + p * 16 * WST2 * 4 + kcb);
                bw[2*p][0] = r0; bw[2*p][1] = r1; bw[2*p+1][0] = r2; bw[2*p+1][1] = r3;
            }
            #pragma unroll
            for (int mt = 0; mt < 4; ++mt) {
                uint32_t a0, a1, a2, a3;
                LDSM4(a0, a1, a2, a3, stb + a_off + mt * 16 * WST2 * 4 + kcb);
                #pragma unroll
                for (int nt = 0; nt < 4; ++nt)
                    mma_f16(acc[mt][nt], a0, a1, a2, a3, bw[nt][0], bw[nt][1]);
            }
        }
        if (t + 3 < ntiles) issue(t + 3);
        CP_COMMIT();
    }

    // ---- epilogue ----
    #pragma unroll
    for (int mt = 0; mt < 4; ++mt) {
        #pragma unroll
        for (int nt = 0; nt < 4; ++nt) {
            int row = bm + wm + mt * 16 + gid;
            int col = bn + wn + nt * 8 + tig * 2;
            float2 v0 = make_float2(acc[mt][nt][0], acc[mt][nt][1]);
            float2 v1 = make_float2(acc[mt][nt][2], acc[mt][nt][3]);
            if (EPI == EPI_BIAS_RES || EPI == EPI_SILU_H) {
                float bx = bias[col], by = bias[col + 1];
                v0.x += bx; v0.y += by; v1.x += bx; v1.y += by;
            }
            if (EPI == EPI_BIAS_RES) {
                float2 r0 = *(const float2*)(res + (size_t)row * N + col);
                float2 r1 = *(const float2*)(res + (size_t)(row + 8) * N + col);
                v0.x += r0.x; v0.y += r0.y; v1.x += r1.x; v1.y += r1.y;
                *(float2*)(C + (size_t)row * N + col)       = v0;
                *(float2*)(C + (size_t)(row + 8) * N + col) = v1;
            } else if (EPI == EPI_SILU_H) {
                v0.x *= 1.f / (1.f + __expf(-v0.x));
                v0.y *= 1.f / (1.f + __expf(-v0.y));
                v1.x *= 1.f / (1.f + __expf(-v1.x));
                v1.y *= 1.f / (1.f + __expf(-v1.y));
                *(uint32_t*)(H0 + (size_t)row * N + col)       = cvt2h(v0.x, v0.y);
                *(uint32_t*)(H0 + (size_t)(row + 8) * N + col) = cvt2h(v1.x, v1.y);
            } else if (EPI == EPI_QKV) {
                int region = col >> 10;
                int colr   = col & 1023;
                __half* dst = (region == 0) ? H0 : (region == 1) ? H1 : H2;
                float sc = (region == 0) ? 0.125f : 1.0f;
                *(uint32_t*)(dst + (size_t)row * DIM + colr) =
                    cvt2h(v0.x * sc, v0.y * sc);
                *(uint32_t*)(dst + (size_t)(row + 8) * DIM + colr) =
                    cvt2h(v1.x * sc, v1.y * sc);
            } else {
                *(float2*)(C + (size_t)row * N + col)       = v0;
                *(float2*)(C + (size_t)(row + 8) * N + col) = v1;
            }
        }
    }
}

// ---------------- Flash attention fp16: cp.async K/V ring + trans-V --------
#define AST 36
#define WQW (128 * AST)
#define KVSTG (128 * AST)                 // 64 K rows + 64 V rows per stage
#define NKV 3
#define ATTN_WORDS (WQW + NKV * KVSTG)
#define ATTN_SM_BYTES (ATTN_WORDS * 4)    // 73728

__global__ __launch_bounds__(256, 2) void attn_f16(
    const __half* __restrict__ Qg, const __half* __restrict__ Kg,
    const __half* __restrict__ Vg, __half* __restrict__ o)
{
    extern __shared__ uint32_t smw[];
    uint32_t sbase = (uint32_t)__cvta_generic_to_shared(smw);

    int tid  = threadIdx.x;
    int warp = tid >> 5, lane = tid & 31;
    int gid  = lane >> 2, tig = lane & 3;
    int qrow0 = warp * 16;

    int qb = blockIdx.x;
    int b  = blockIdx.y >> 4;
    int h  = blockIdx.y & 15;

    uint32_t aoff  = (uint32_t)((((lane & 15)) * AST + (lane >> 4) * 4) * 4);
    uint32_t kboff = (uint32_t)(((((lane >> 4) & 1) * 8 + (lane & 7)) * AST
                                 + ((lane >> 3) & 1) * 4) * 4);
    uint32_t vboff = (uint32_t)((((lane & 7) + ((lane >> 3) & 1) * 8) * AST
                                 + ((lane >> 4) & 1) * 4) * 4);

    const __half* qg = Qg + (size_t)(b * SEQ + qb * 128) * DIM + h * HD;
    const __half* kbase = Kg + (size_t)(b * SEQ) * DIM + h * HD;
    const __half* vbase = Vg + (size_t)(b * SEQ) * DIM + h * HD;

    auto issueKV = [&](int jb, int st) {
        const __half* kg = kbase + (size_t)(jb * 64) * DIM;
        const __half* vg = vbase + (size_t)(jb * 64) * DIM;
        uint32_t kst = sbase + (WQW + st * KVSTG) * 4;
        uint32_t vst = kst + 64 * AST * 4;
        #pragma unroll
        for (int c = 0; c < 2; ++c) {
            int ch = tid + c * 256;                   // 0..511
            int r = ch >> 3, cw = ch & 7;
            uint32_t off = (uint32_t)(r * AST + cw * 4) * 4;
            CP16(kst + off, kg + (size_t)r * DIM + cw * 8);
            CP16(vst + off, vg + (size_t)r * DIM + cw * 8);
        }
    };

    // prologue: Q + KV(0) -> group0, KV(1) -> group1
    issueKV(0, 0);
    #pragma unroll
    for (int c = 0; c < 4; ++c) {
        int ch = tid + c * 256;                       // 0..1023
        int r = ch >> 3, cw = ch & 7;
        CP16(sbase + (uint32_t)(r * AST + cw * 4) * 4, qg + (size_t)r * DIM + cw * 8);
    }
    CP_COMMIT();
    issueKV(1, 1);
    CP_COMMIT();

    CP_WAIT1();            // group0 done: Q + KV(0)
    __syncthreads();
    uint32_t qf[4][4];
    #pragma unroll
    for (int kcx = 0; kcx < 4; ++kcx)
        LDSM4(qf[kcx][0], qf[kcx][1], qf[kcx][2], qf[kcx][3],
              sbase + (uint32_t)(qrow0 * AST) * 4 + aoff + kcx * 32);

    float m0 = -1e30f, m1 = -1e30f, l0r = 0.f, l1r = 0.f;
    float oacc[8][4];
    #pragma unroll
    for (int nt = 0; nt < 8; nt++)
        #pragma unroll
        for (int r = 0; r < 4; r++) oacc[nt][r] = 0.f;

    for (int jb = 0; jb < SEQ / 64; ++jb) {
        if (jb > 0) { CP_WAIT1(); __syncthreads(); }
        if (jb + 2 < SEQ / 64) issueKV(jb + 2, (jb + 2) % NKV);
        CP_COMMIT();

        uint32_t kst4 = sbase + (WQW + (jb % NKV) * KVSTG) * 4;
        uint32_t vst4 = kst4 + 64 * AST * 4;

        // ---- S = Q K^T ----
        float s[8][4];
        #pragma unroll
        for (int nt = 0; nt < 8; nt++)
            #pragma unroll
            for (int r = 0; r < 4; r++) s[nt][r] = 0.f;

        #pragma unroll
        for (int kcx = 0; kcx < 4; ++kcx) {
            uint32_t kcb = kcx * 32;
            #pragma unroll
            for (int p = 0; p < 4; ++p) {
                uint32_t r0, r1, r2, r3;
                LDSM4(r0, r1, r2, r3, kst4 + p * 16 * AST * 4 + kboff + kcb);
                mma_f16(s[2*p],   qf[kcx][0], qf[kcx][1], qf[kcx][2], qf[kcx][3], r0, r1);
                mma_f16(s[2*p+1], qf[kcx][0], qf[kcx][1], qf[kcx][2], qf[kcx][3], r2, r3);
            }
        }

        // ---- online softmax ----
        float mc0 = s[0][0], mc1 = s[0][2];
        #pragma unroll
        for (int nt = 0; nt < 8; ++nt) {
            mc0 = fmaxf(mc0, fmaxf(s[nt][0], s[nt][1]));
            mc1 = fmaxf(mc1, fmaxf(s[nt][2], s[nt][3]));
        }
        mc0 = fmaxf(mc0, __shfl_xor_sync(0xffffffffu, mc0, 1));
        mc0 = fmaxf(mc0, __shfl_xor_sync(0xffffffffu, mc0, 2));
        mc1 = fmaxf(mc1, __shfl_xor_sync(0xffffffffu, mc1, 1));
        mc1 = fmaxf(mc1, __shfl_xor_sync(0xffffffffu, mc1, 2));
        float mn0 = fmaxf(m0, mc0), mn1 = fmaxf(m1, mc1);
        float f0 = __expf(m0 - mn0), f1 = __expf(m1 - mn1);
        m0 = mn0; m1 = mn1;

        float ps0 = 0.f, ps1 = 0.f;
        #pragma unroll
        for (int nt = 0; nt < 8; ++nt) {
            float p0 = __expf(s[nt][0] - m0);
            float p1 = __expf(s[nt][1] - m0);
            float p2 = __expf(s[nt][2] - m1);
            float p3 = __expf(s[nt][3] - m1);
            ps0 += p0 + p1; ps1 += p2 + p3;
            s[nt][0] = p0; s[nt][1] = p1; s[nt][2] = p2; s[nt][3] = p3;
        }
        ps0 += __shfl_xor_sync(0xffffffffu, ps0, 1);
        ps0 += __shfl_xor_sync(0xffffffffu, ps0, 2);
        ps1 += __shfl_xor_sync(0xffffffffu, ps1, 1);
        ps1 += __shfl_xor_sync(0xffffffffu, ps1, 2);
        l0r = l0r * f0 + ps0;
        l1r = l1r * f1 + ps1;
        bool need = (f0 != 1.0f) || (f1 != 1.0f);
        if (__any_sync(0xffffffffu, need)) {
            #pragma unroll
            for (int nt = 0; nt < 8; ++nt) {
                oacc[nt][0] *= f0; oacc[nt][1] *= f0;
                oacc[nt][2] *= f1; oacc[nt][3] *= f1;
            }
        }

        // ---- O += P V (register repack; V via trans-ldmatrix) ----
        #pragma unroll
        for (int kcx = 0; kcx < 4; ++kcx) {
            uint32_t pa0 = cvt2h(s[2*kcx][0],   s[2*kcx][1]);
            uint32_t pa1 = cvt2h(s[2*kcx][2],   s[2*kcx][3]);
            uint32_t pa2 = cvt2h(s[2*kcx+1][0], s[2*kcx+1][1]);
            uint32_t pa3 = cvt2h(s[2*kcx+1][2], s[2*kcx+1][3]);
            #pragma unroll
            for (int p = 0; p < 4; ++p) {
                uint32_t r0, r1, r2, r3;
                LDSM4T(r0, r1, r2, r3,
                       vst4 + vboff + (uint32_t)(kcx * 16 * AST + p * 8) * 4);
                mma_f16(oacc[2*p],   pa0, pa1, pa2, pa3, r0, r1);
                mma_f16(oacc[2*p+1], pa0, pa1, pa2, pa3, r2, r3);
            }
        }
    }

    float inv0 = 1.0f / l0r, inv1 = 1.0f / l1r;
    int grow0 = b * SEQ + qb * 128 + qrow0 + gid;
    #pragma unroll
    for (int nt = 0; nt < 8; ++nt) {
        int col = h * HD + nt * 8 + tig * 2;
        *(uint32_t*)(o + (size_t)grow0 * DIM + col) =
            cvt2h(oacc[nt][0] * inv0, oacc[nt][1] * inv0);
        *(uint32_t*)(o + (size_t)(grow0 + 8) * DIM + col) =
            cvt2h(oacc[nt][2] * inv1, oacc[nt][3] * inv1);
    }
}

// ---------------- launch ----------------
extern "C" void kernel_launch(void* const* d_in, const int* in_sizes, int n_in,
                              void* d_out, int out_size)
{
    const float* x     = (const float*)d_in[0];
    const float* qkv_w = (const float*)d_in[1];
    const float* out_w = (const float*)d_in[2];
    const float* out_b = (const float*)d_in[3];
    const float* ff_w1 = (const float*)d_in[4];
    const float* ff_b1 = (const float*)d_in[5];
    const float* ff_w2 = (const float*)d_in[6];
    const float* ff_b2 = (const float*)d_in[7];
    const float* ln1_w = (const float*)d_in[8];
    const float* ln1_b = (const float*)d_in[9];
    const float* ln2_w = (const float*)d_in[10];
    const float* ln2_b = (const float*)d_in[11];
    float* out = (float*)d_out;

    float *x1;
    __half *xln, *q, *k, *v, *attn, *xln2, *hbuf;
    __half *wq, *wo, *w1, *w2;
    cudaGetSymbolAddress((void**)&x1,   g_x1);
    cudaGetSymbolAddress((void**)&xln,  g_xln);
    cudaGetSymbolAddress((void**)&q,    g_q);
    cudaGetSymbolAddress((void**)&k,    g_k);
    cudaGetSymbolAddress((void**)&v,    g_v);
    cudaGetSymbolAddress((void**)&attn, g_attn);
    cudaGetSymbolAddress((void**)&xln2, g_xln2);
    cudaGetSymbolAddress((void**)&hbuf, g_h);
    cudaGetSymbolAddress((void**)&wq,   g_wqkv);
    cudaGetSymbolAddress((void**)&wo,   g_wout);
    cudaGetSymbolAddress((void**)&w1,   g_w1);
    cudaGetSymbolAddress((void**)&w2,   g_w2);

    cudaFuncSetAttribute(gemm_f16<EPI_QKV>,
        cudaFuncAttributeMaxDynamicSharedMemorySize, GEMM_SMEM);
    cudaFuncSetAttribute(gemm_f16<EPI_BIAS_RES>,
        cudaFuncAttributeMaxDynamicSharedMemorySize, GEMM_SMEM);
    cudaFuncSetAttribute(gemm_f16<EPI_SILU_H>,
        cudaFuncAttributeMaxDynamicSharedMemorySize, GEMM_SMEM);
    cudaFuncSetAttribute(attn_f16,
        cudaFuncAttributeMaxDynamicSharedMemorySize, ATTN_SM_BYTES);

    // 0. convert all weights to fp16 (single launch)
    conv_all<<<(CB3 + 1023) / 1024, 256>>>(qkv_w, out_w, ff_w1, ff_w2, wq, wo, w1, w2);

    // 1. LN1 -> fp16
    ln_kernel<<<TOK / 8, 256>>>(x, ln1_w, ln1_b, xln);
    // 2. QKV -> fp16 q(scaled)/k/v
    gemm_f16<EPI_QKV><<<dim3(3 * DIM / 128, TOK / 128), 256, GEMM_SMEM>>>(
        xln, wq, nullptr, nullptr, nullptr, q, k, v, TOK, 3 * DIM, DIM);
    // 3. attention -> fp16
    attn_f16<<<dim3(SEQ / 128, 2 * NHEAD), 256, ATTN_SM_BYTES>>>(q, k, v, attn);
    // 4. x1 = x + attn @ out_w^T + out_b -> fp32
    gemm_f16<EPI_BIAS_RES><<<dim3(DIM / 128, TOK / 128), 256, GEMM_SMEM>>>(
        attn, wo, out_b, x, x1, nullptr, nullptr, nullptr, TOK, DIM, DIM);
    // 5. LN2 -> fp16
    ln_kernel<<<TOK / 8, 256>>>(x1, ln2_w, ln2_b, xln2);
    // 6. h = silu(...) -> fp16
    gemm_f16<EPI_SILU_H><<<dim3(MLPD / 128, TOK / 128), 256, GEMM_SMEM>>>(
        xln2, w1, ff_b1, nullptr, nullptr, hbuf, nullptr, nullptr, TOK, MLPD, DIM);
    // 7. out = x1 + h @ ff_w2^T + ff_b2 -> fp32
    gemm_f16<EPI_BIAS_RES><<<dim3(DIM / 128, TOK / 128), 256, GEMM_SMEM>>>(
        hbuf, w2, ff_b2, x1, out, nullptr, nullptr, nullptr, TOK, DIM, MLPD);
}

// round 16
// speedup vs baseline: 1.1130x; 1.0046x over previous
#include <cuda_runtime.h>
#include <cuda_fp16.h>
#include <math.h>
#include <stdint.h>

#define TOK   4096
#define DIM   1024
#define MLPD  4096
#define NHEAD 16
#define HD    64
#define SEQ   2048

// ---------------- scratch ----------------
__device__ float g_x1  [TOK * DIM];
__device__ __half g_xln [TOK * DIM];
__device__ __half g_q   [TOK * DIM];   // Q (scaled by 0.125*log2(e))
__device__ __half g_k   [TOK * DIM];   // K
__device__ __half g_v   [TOK * DIM];   // V
__device__ __half g_attn[TOK * DIM];
__device__ __half g_xln2[TOK * DIM];
__device__ __half g_h   [TOK * MLPD];
__device__ __half g_wqkv[3 * DIM * DIM];
__device__ __half g_wout[DIM * DIM];
__device__ __half g_w1  [MLPD * DIM];
__device__ __half g_w2  [DIM * MLPD];

// ---------------- helpers ----------------
__device__ __forceinline__ uint32_t cvt2h(float x, float y) {
    __half2 h = __floats2half2_rn(x, y);
    return *(uint32_t*)&h;
}

__device__ __forceinline__ void mma_f16(float* d,
    uint32_t a0, uint32_t a1, uint32_t a2, uint32_t a3,
    uint32_t b0, uint32_t b1)
{
    asm volatile(
        "mma.sync.aligned.m16n8k16.row.col.f32.f16.f16.f32 "
        "{%0,%1,%2,%3}, {%4,%5,%6,%7}, {%8,%9}, {%0,%1,%2,%3};"
        : "+f"(d[0]), "+f"(d[1]), "+f"(d[2]), "+f"(d[3])
        : "r"(a0), "r"(a1), "r"(a2), "r"(a3), "r"(b0), "r"(b1));
}

#define LDSM4(R0,R1,R2,R3,ADDR) \
    asm volatile("ldmatrix.sync.aligned.m8n8.x4.shared.b16 {%0,%1,%2,%3}, [%4];" \
        : "=r"(R0), "=r"(R1), "=r"(R2), "=r"(R3) : "r"(ADDR))
#define LDSM4T(R0,R1,R2,R3,ADDR) \
    asm volatile("ldmatrix.sync.aligned.m8n8.x4.trans.shared.b16 {%0,%1,%2,%3}, [%4];" \
        : "=r"(R0), "=r"(R1), "=r"(R2), "=r"(R3) : "r"(ADDR))

#define CP16(dst, src) \
    asm volatile("cp.async.ca.shared.global [%0], [%1], 16;" :: "r"(dst), "l"(src) : "memory")
#define CP_COMMIT() asm volatile("cp.async.commit_group;" ::: "memory")
#define CP_WAIT2()  asm volatile("cp.async.wait_group 2;" ::: "memory")
#define CP_WAIT1()  asm volatile("cp.async.wait_group 1;" ::: "memory")

// ---------------- merged weight convert (fp32 -> fp16) ----------------
#define CB0 (3 * DIM * DIM / 4)
#define CB1 (CB0 + DIM * DIM / 4)
#define CB2 (CB1 + MLPD * DIM / 4)
#define CB3 (CB2 + DIM * MLPD / 4)

__global__ __launch_bounds__(256) void conv_all(
    const float* __restrict__ s0, const float* __restrict__ s1,
    const float* __restrict__ s2, const float* __restrict__ s3,
    __half* __restrict__ d0, __half* __restrict__ d1,
    __half* __restrict__ d2, __half* __restrict__ d3)
{
    int i0 = blockIdx.x * 1024 + threadIdx.x;
    #pragma unroll
    for (int k2 = 0; k2 < 4; ++k2) {
        int i = i0 + k2 * 256;
        if (i < CB3) {
            const float* sp; __half* dp; int off;
            if (i < CB0)      { sp = s0; dp = d0; off = i; }
            else if (i < CB1) { sp = s1; dp = d1; off = i - CB0; }
            else if (i < CB2) { sp = s2; dp = d2; off = i - CB1; }
            else              { sp = s3; dp = d3; off = i - CB2; }
            float4 v = ((const float4*)sp)[off];
            ((uint2*)dp)[off] = make_uint2(cvt2h(v.x, v.y), cvt2h(v.z, v.w));
        }
    }
}

// ---------------- LayerNorm, warp-per-row ----------------
__global__ __launch_bounds__(256) void ln_kernel(
    const float* __restrict__ x, const float* __restrict__ w,
    const float* __restrict__ b, __half* __restrict__ o)
{
    int warp = threadIdx.x >> 5, lane = threadIdx.x & 31;
    int row = blockIdx.x * 8 + warp;
    const float4* xr = (const float4*)(x + (size_t)row * DIM);
    float4 v[8];
    float s = 0.f, sq = 0.f;
    #pragma unroll
    for (int i = 0; i < 8; i++) {
        v[i] = xr[lane + i * 32];
        s  += v[i].x + v[i].y + v[i].z + v[i].w;
        sq += v[i].x*v[i].x + v[i].y*v[i].y + v[i].z*v[i].z + v[i].w*v[i].w;
    }
    #pragma unroll
    for (int of = 16; of > 0; of >>= 1) {
        s  += __shfl_xor_sync(0xffffffffu, s,  of);
        sq += __shfl_xor_sync(0xffffffffu, sq, of);
    }
    float mean = s * (1.0f / DIM);
    float rstd = rsqrtf(sq * (1.0f / DIM) - mean * mean + 1e-5f);
    uint2* orow = (uint2*)o + (size_t)row * (DIM / 4);
    #pragma unroll
    for (int i = 0; i < 8; i++) {
        int idx = lane + i * 32;
        float4 wv = ((const float4*)w)[idx];
        float4 bv = ((const float4*)b)[idx];
        float ox = (v[i].x - mean) * rstd * wv.x + bv.x;
        float oy = (v[i].y - mean) * rstd * wv.y + bv.y;
        float oz = (v[i].z - mean) * rstd * wv.z + bv.z;
        float ow = (v[i].w - mean) * rstd * wv.w + bv.w;
        orow[idx] = make_uint2(cvt2h(ox, oy), cvt2h(oz, ow));
    }
}

// ---------------- NT GEMM fp16, KT=32, 4-stage cp.async, ldmatrix ----------
#define EPI_NONE      0
#define EPI_BIAS_RES  1
#define EPI_SILU_H    2
#define EPI_QKV       3

#define WST2 20
#define PLW2 (128 * WST2)
#define STGW2 (2 * PLW2)
#define NSTAGE 4
#define GEMM_SMEM (NSTAGE * STGW2 * 4)   // 81920

template <int EPI>
__global__ __launch_bounds__(256, 2) void gemm_f16(
    const __half* __restrict__ A, const __half* __restrict__ W,
    const float* __restrict__ bias, const float* __restrict__ res,
    float* __restrict__ C,
    __half* __restrict__ H0, __half* __restrict__ H1, __half* __restrict__ H2,
    int M, int N, int K)
{
    extern __shared__ __align__(16) uint32_t smw[];
    uint32_t sbase = (uint32_t)__cvta_generic_to_shared(smw);

    int tid  = threadIdx.x;
    int warp = tid >> 5, lane = tid & 31;
    int bm   = blockIdx.y * 128;
    int bn   = blockIdx.x * 128;
    int wm   = (warp & 1) * 64;
    int wn   = (warp >> 1) * 32;
    int gid  = lane >> 2, tig = lane & 3;

    int lrow  = tid >> 1;
    int lh    = tid & 1;
    const __half* pA = A + (size_t)(bm + lrow) * K + lh * 16;
    const __half* pW = W + (size_t)(bn + lrow) * K + lh * 16;
    uint32_t dstb = (uint32_t)(lrow * WST2 + lh * 8) * 4;

    uint32_t a_off = (uint32_t)(((wm + (lane & 15)) * WST2 + (lane >> 4) * 4) * 4);
    uint32_t b_off = (uint32_t)(((wn + ((lane >> 4) & 1) * 8 + (lane & 7)) * WST2
                                 + ((lane >> 3) & 1) * 4) * 4);

    float acc[4][4][4];
    #pragma unroll
    for (int i = 0; i < 4; i++)
        #pragma unroll
        for (int j = 0; j < 4; j++)
            #pragma unroll
            for (int r = 0; r < 4; r++) acc[i][j][r] = 0.f;

    int ntiles = K >> 5;

    auto issue = [&](int t) {
        uint32_t base = sbase + ((t % NSTAGE) * STGW2) * 4 + dstb;
        const __half* a = pA + (size_t)t * 32;
        const __half* w = pW + (size_t)t * 32;
        CP16(base,               a);
        CP16(base + 16,          a + 8);
        CP16(base + PLW2*4,      w);
        CP16(base + PLW2*4 + 16, w + 8);
    };

    issue(0); CP_COMMIT();
    issue(1); CP_COMMIT();
    issue(2); CP_COMMIT();

    for (int t = 0; t < ntiles; ++t) {
        CP_WAIT2();
        __syncthreads();
        // prefetch next stage EARLY: stage (t+3)%4 == (t-1)%4, fully consumed
        if (t + 3 < ntiles) issue(t + 3);
        CP_COMMIT();
        uint32_t stb = sbase + ((t % NSTAGE) * STGW2) * 4;

        #pragma unroll
        for (int kc = 0; kc < 2; ++kc) {
            uint32_t kcb = kc * 32;
            uint32_t bw[4][2];
            #pragma unroll
            for (int p = 0; p < 2; ++p) {
                uint32_t r0, r1, r2, r3;
                LDSM4(r0, r1, r2, r3, stb + PLW2*4 + b_off + p * 16 * WST2 * 4 + kcb);
                bw[2*p][0] = r0; bw[2*p][1] = r1; bw[2*p+1][0] = r2; bw[2*p+1][1] = r3;
            }
            #pragma unroll
            for (int mt = 0; mt < 4; ++mt) {
                uint32_t a0, a1, a2, a3;
                LDSM4(a0, a1, a2, a3, stb + a_off + mt * 16 * WST2 * 4 + kcb);
                #pragma unroll
                for (int nt = 0; nt < 4; ++nt)
                    mma_f16(acc[mt][nt], a0, a1, a2, a3, bw[nt][0], bw[nt][1]);
            }
        }
    }

    // ---- epilogue ----
    #pragma unroll
    for (int mt = 0; mt < 4; ++mt) {
        #pragma unroll
        for (int nt = 0; nt < 4; ++nt) {
            int row = bm + wm + mt * 16 + gid;
            int col = bn + wn + nt * 8 + tig * 2;
            float2 v0 = make_float2(acc[mt][nt][0], acc[mt][nt][1]);
            float2 v1 = make_float2(acc[mt][nt][2], acc[mt][nt][3]);
            if (EPI == EPI_BIAS_RES || EPI == EPI_SILU_H) {
                float bx = bias[col], by = bias[col + 1];
                v0.x += bx; v0.y += by; v1.x += bx; v1.y += by;
            }
            if (EPI == EPI_BIAS_RES) {
                float2 r0 = *(const float2*)(res + (size_t)row * N + col);
                float2 r1 = *(const float2*)(res + (size_t)(row + 8) * N + col);
                v0.x += r0.x; v0.y += r0.y; v1.x += r1.x; v1.y += r1.y;
                *(float2*)(C + (size_t)row * N + col)       = v0;
                *(float2*)(C + (size_t)(row + 8) * N + col) = v1;
            } else if (EPI == EPI_SILU_H) {
                v0.x *= 1.f / (1.f + __expf(-v0.x));
                v0.y *= 1.f / (1.f + __expf(-v0.y));
                v1.x *= 1.f / (1.f + __expf(-v1.x));
                v1.y *= 1.f / (1.f + __expf(-v1.y));
                *(uint32_t*)(H0 + (size_t)row * N + col)       = cvt2h(v0.x, v0.y);
                *(uint32_t*)(H0 + (size_t)(row + 8) * N + col) = cvt2h(v1.x, v1.y);
            } else if (EPI == EPI_QKV) {
                int region = col >> 10;
                int colr   = col & 1023;
                __half* dst = (region == 0) ? H0 : (region == 1) ? H1 : H2;
                // Q pre-scaled by 1/sqrt(hd) * log2(e) for base-2 softmax
                float sc = (region == 0) ? 0.125f * 1.44269504f : 1.0f;
                *(uint32_t*)(dst + (size_t)row * DIM + colr) =
                    cvt2h(v0.x * sc, v0.y * sc);
                *(uint32_t*)(dst + (size_t)(row + 8) * DIM + colr) =
                    cvt2h(v1.x * sc, v1.y * sc);
            } else {
                *(float2*)(C + (size_t)row * N + col)       = v0;
                *(float2*)(C + (size_t)(row + 8) * N + col) = v1;
            }
        }
    }
}

// ---------------- Flash attention fp16: cp.async K/V ring + trans-V --------
#define AST 36
#define WQW (128 * AST)
#define KVSTG (128 * AST)                 // 64 K rows + 64 V rows per stage
#define NKV 3
#define ATTN_WORDS (WQW + NKV * KVSTG)
#define ATTN_SM_BYTES (ATTN_WORDS * 4)    // 73728

__global__ __launch_bounds__(256, 2) void attn_f16(
    const __half* __restrict__ Qg, const __half* __restrict__ Kg,
    const __half* __restrict__ Vg, __half* __restrict__ o)
{
    extern __shared__ uint32_t smw[];
    uint32_t sbase = (uint32_t)__cvta_generic_to_shared(smw);

    int tid  = threadIdx.x;
    int warp = tid >> 5, lane = tid & 31;
    int gid  = lane >> 2, tig = lane & 3;
    int qrow0 = warp * 16;

    int qb = blockIdx.x;
    int b  = blockIdx.y >> 4;
    int h  = blockIdx.y & 15;

    uint32_t aoff  = (uint32_t)((((lane & 15)) * AST + (lane >> 4) * 4) * 4);
    uint32_t kboff = (uint32_t)(((((lane >> 4) & 1) * 8 + (lane & 7)) * AST
                                 + ((lane >> 3) & 1) * 4) * 4);
    uint32_t vboff = (uint32_t)((((lane & 7) + ((lane >> 3) & 1) * 8) * AST
                                 + ((lane >> 4) & 1) * 4) * 4);

    const __half* qg = Qg + (size_t)(b * SEQ + qb * 128) * DIM + h * HD;
    const __half* kbase = Kg + (size_t)(b * SEQ) * DIM + h * HD;
    const __half* vbase = Vg + (size_t)(b * SEQ) * DIM + h * HD;

    auto issueKV = [&](int jb, int st) {
        const __half* kg = kbase + (size_t)(jb * 64) * DIM;
        const __half* vg = vbase + (size_t)(jb * 64) * DIM;
        uint32_t kst = sbase + (WQW + st * KVSTG) * 4;
        uint32_t vst = kst + 64 * AST * 4;
        #pragma unroll
        for (int c = 0; c < 2; ++c) {
            int ch = tid + c * 256;                   // 0..511
            int r = ch >> 3, cw = ch & 7;
            uint32_t off = (uint32_t)(r * AST + cw * 4) * 4;
            CP16(kst + off, kg + (size_t)r * DIM + cw * 8);
            CP16(vst + off, vg + (size_t)r * DIM + cw * 8);
        }
    };

    // prologue: Q + KV(0) -> group0, KV(1) -> group1
    issueKV(0, 0);
    #pragma unroll
    for (int c = 0; c < 4; ++c) {
        int ch = tid + c * 256;
        int r = ch >> 3, cw = ch & 7;
        CP16(sbase + (uint32_t)(r * AST + cw * 4) * 4, qg + (size_t)r * DIM + cw * 8);
    }
    CP_COMMIT();
    issueKV(1, 1);
    CP_COMMIT();

    CP_WAIT1();
    __syncthreads();
    uint32_t qf[4][4];
    #pragma unroll
    for (int kcx = 0; kcx < 4; ++kcx)
        LDSM4(qf[kcx][0], qf[kcx][1], qf[kcx][2], qf[kcx][3],
              sbase + (uint32_t)(qrow0 * AST) * 4 + aoff + kcx * 32);

    float m0 = -1e30f, m1 = -1e30f, l0r = 0.f, l1r = 0.f;
    float oacc[8][4];
    #pragma unroll
    for (int nt = 0; nt < 8; nt++)
        #pragma unroll
        for (int r = 0; r < 4; r++) oacc[nt][r] = 0.f;

    for (int jb = 0; jb < SEQ / 64; ++jb) {
        if (jb > 0) { CP_WAIT1(); __syncthreads(); }
        if (jb + 2 < SEQ / 64) issueKV(jb + 2, (jb + 2) % NKV);
        CP_COMMIT();

        uint32_t kst4 = sbase + (WQW + (jb % NKV) * KVSTG) * 4;
        uint32_t vst4 = kst4 + 64 * AST * 4;

        // ---- S = Q K^T (base-2 scaled) ----
        float s[8][4];
        #pragma unroll
        for (int nt = 0; nt < 8; nt++)
            #pragma unroll
            for (int r = 0; r < 4; r++) s[nt][r] = 0.f;

        #pragma unroll
        for (int kcx = 0; kcx < 4; ++kcx) {
            uint32_t kcb = kcx * 32;
            #pragma unroll
            for (int p = 0; p < 4; ++p) {
                uint32_t r0, r1, r2, r3;
                LDSM4(r0, r1, r2, r3, kst4 + p * 16 * AST * 4 + kboff + kcb);
                mma_f16(s[2*p],   qf[kcx][0], qf[kcx][1], qf[kcx][2], qf[kcx][3], r0, r1);
                mma_f16(s[2*p+1], qf[kcx][0], qf[kcx][1], qf[kcx][2], qf[kcx][3], r2, r3);
            }
        }

        // ---- online softmax (base-2: exp2 only) ----
        float mc0 = s[0][0], mc1 = s[0][2];
        #pragma unroll
        for (int nt = 0; nt < 8; ++nt) {
            mc0 = fmaxf(mc0, fmaxf(s[nt][0], s[nt][1]));
            mc1 = fmaxf(mc1, fmaxf(s[nt][2], s[nt][3]));
        }
        mc0 = fmaxf(mc0, __shfl_xor_sync(0xffffffffu, mc0, 1));
        mc0 = fmaxf(mc0, __shfl_xor_sync(0xffffffffu, mc0, 2));
        mc1 = fmaxf(mc1, __shfl_xor_sync(0xffffffffu, mc1, 1));
        mc1 = fmaxf(mc1, __shfl_xor_sync(0xffffffffu, mc1, 2));
        float mn0 = fmaxf(m0, mc0), mn1 = fmaxf(m1, mc1);
        float f0 = exp2f(m0 - mn0), f1 = exp2f(m1 - mn1);
        m0 = mn0; m1 = mn1;

        float ps0 = 0.f, ps1 = 0.f;
        #pragma unroll
        for (int nt = 0; nt < 8; ++nt) {
            float p0 = exp2f(s[nt][0] - m0);
            float p1 = exp2f(s[nt][1] - m0);
            float p2 = exp2f(s[nt][2] - m1);
            float p3 = exp2f(s[nt][3] - m1);
            ps0 += p0 + p1; ps1 += p2 + p3;
            s[nt][0] = p0; s[nt][1] = p1; s[nt][2] = p2; s[nt][3] = p3;
        }
        ps0 += __shfl_xor_sync(0xffffffffu, ps0, 1);
        ps0 += __shfl_xor_sync(0xffffffffu, ps0, 2);
        ps1 += __shfl_xor_sync(0xffffffffu, ps1, 1);
        ps1 += __shfl_xor_sync(0xffffffffu, ps1, 2);
        l0r = l0r * f0 + ps0;
        l1r = l1r * f1 + ps1;
        bool need = (f0 != 1.0f) || (f1 != 1.0f);
        if (__any_sync(0xffffffffu, need)) {
            #pragma unroll
            for (int nt = 0; nt < 8; ++nt) {
                oacc[nt][0] *= f0; oacc[nt][1] *= f0;
                oacc[nt][2] *= f1; oacc[nt][3] *= f1;
            }
        }

        // ---- O += P V (register repack; V via trans-ldmatrix) ----
        #pragma unroll
        for (int kcx = 0; kcx < 4; ++kcx) {
            uint32_t pa0 = cvt2h(s[2*kcx][0],   s[2*kcx][1]);
            uint32_t pa1 = cvt2h(s[2*kcx][2],   s[2*kcx][3]);
            uint32_t pa2 = cvt2h(s[2*kcx+1][0], s[2*kcx+1][1]);
            uint32_t pa3 = cvt2h(s[2*kcx+1][2], s[2*kcx+1][3]);
            #pragma unroll
            for (int p = 0; p < 4; ++p) {
                uint32_t r0, r1, r2, r3;
                LDSM4T(r0, r1, r2, r3,
                       vst4 + vboff + (uint32_t)(kcx * 16 * AST + p * 8) * 4);
                mma_f16(oacc[2*p],   pa0, pa1, pa2, pa3, r0, r1);
                mma_f16(oacc[2*p+1], pa0, pa1, pa2, pa3, r2, r3);
            }
        }
    }

    float inv0 = 1.0f / l0r, inv1 = 1.0f / l1r;
    int grow0 = b * SEQ + qb * 128 + qrow0 + gid;
    #pragma unroll
    for (int nt = 0; nt < 8; ++nt) {
        int col = h * HD + nt * 8 + tig * 2;
        *(uint32_t*)(o + (size_t)grow0 * DIM + col) =
            cvt2h(oacc[nt][0] * inv0, oacc[nt][1] * inv0);
        *(uint32_t*)(o + (size_t)(grow0 + 8) * DIM + col) =
            cvt2h(oacc[nt][2] * inv1, oacc[nt][3] * inv1);
    }
}

// ---------------- launch ----------------
extern "C" void kernel_launch(void* const* d_in, const int* in_sizes, int n_in,
                              void* d_out, int out_size)
{
    const float* x     = (const float*)d_in[0];
    const float* qkv_w = (const float*)d_in[1];
    const float* out_w = (const float*)d_in[2];
    const float* out_b = (const float*)d_in[3];
    const float* ff_w1 = (const float*)d_in[4];
    const float* ff_b1 = (const float*)d_in[5];
    const float* ff_w2 = (const float*)d_in[6];
    const float* ff_b2 = (const float*)d_in[7];
    const float* ln1_w = (const float*)d_in[8];
    const float* ln1_b = (const float*)d_in[9];
    const float* ln2_w = (const float*)d_in[10];
    const float* ln2_b = (const float*)d_in[11];
    float* out = (float*)d_out;

    float *x1;
    __half *xln, *q, *k, *v, *attn, *xln2, *hbuf;
    __half *wq, *wo, *w1, *w2;
    cudaGetSymbolAddress((void**)&x1,   g_x1);
    cudaGetSymbolAddress((void**)&xln,  g_xln);
    cudaGetSymbolAddress((void**)&q,    g_q);
    cudaGetSymbolAddress((void**)&k,    g_k);
    cudaGetSymbolAddress((void**)&v,    g_v);
    cudaGetSymbolAddress((void**)&attn, g_attn);
    cudaGetSymbolAddress((void**)&xln2, g_xln2);
    cudaGetSymbolAddress((void**)&hbuf, g_h);
    cudaGetSymbolAddress((void**)&wq,   g_wqkv);
    cudaGetSymbolAddress((void**)&wo,   g_wout);
    cudaGetSymbolAddress((void**)&w1,   g_w1);
    cudaGetSymbolAddress((void**)&w2,   g_w2);

    cudaFuncSetAttribute(gemm_f16<EPI_QKV>,
        cudaFuncAttributeMaxDynamicSharedMemorySize, GEMM_SMEM);
    cudaFuncSetAttribute(gemm_f16<EPI_BIAS_RES>,
        cudaFuncAttributeMaxDynamicSharedMemorySize, GEMM_SMEM);
    cudaFuncSetAttribute(gemm_f16<EPI_SILU_H>,
        cudaFuncAttributeMaxDynamicSharedMemorySize, GEMM_SMEM);
    cudaFuncSetAttribute(attn_f16,
        cudaFuncAttributeMaxDynamicSharedMemorySize, ATTN_SM_BYTES);

    // 0. convert all weights to fp16 (single launch)
    conv_all<<<(CB3 + 1023) / 1024, 256>>>(qkv_w, out_w, ff_w1, ff_w2, wq, wo, w1, w2);

    // 1. LN1 -> fp16
    ln_kernel<<<TOK / 8, 256>>>(x, ln1_w, ln1_b, xln);
    // 2. QKV -> fp16 q(scaled)/k/v
    gemm_f16<EPI_QKV><<<dim3(3 * DIM / 128, TOK / 128), 256, GEMM_SMEM>>>(
        xln, wq, nullptr, nullptr, nullptr, q, k, v, TOK, 3 * DIM, DIM);
    // 3. attention -> fp16
    attn_f16<<<dim3(SEQ / 128, 2 * NHEAD), 256, ATTN_SM_BYTES>>>(q, k, v, attn);
    // 4. x1 = x + attn @ out_w^T + out_b -> fp32
    gemm_f16<EPI_BIAS_RES><<<dim3(DIM / 128, TOK / 128), 256, GEMM_SMEM>>>(
        attn, wo, out_b, x, x1, nullptr, nullptr, nullptr, TOK, DIM, DIM);
    // 5. LN2 -> fp16
    ln_kernel<<<TOK / 8, 256>>>(x1, ln2_w, ln2_b, xln2);
    // 6. h = silu(...) -> fp16
    gemm_f16<EPI_SILU_H><<<dim3(MLPD / 128, TOK / 128), 256, GEMM_SMEM>>>(
        xln2, w1, ff_b1, nullptr, nullptr, hbuf, nullptr, nullptr, TOK, MLPD, DIM);
    // 7. out = x1 + h @ ff_w2^T + ff_b2 -> fp32
    gemm_f16<EPI_BIAS_RES><<<dim3(DIM / 128, TOK / 128), 256, GEMM_SMEM>>>(
        hbuf, w2, ff_b2, x1, out, nullptr, nullptr, nullptr, TOK, DIM, MLPD);
}

// round 17
// speedup vs baseline: 1.1401x; 1.0243x over previous
#include <cuda_runtime.h>
#include <cuda_fp16.h>
#include <math.h>
#include <stdint.h>

#define TOK   4096
#define DIM   1024
#define MLPD  4096
#define NHEAD 16
#define HD    64
#define SEQ   2048

// ---------------- scratch ----------------
__device__ float g_x1  [TOK * DIM];
__device__ __half g_xln [TOK * DIM];
__device__ __half g_q   [TOK * DIM];   // Q (scaled by 0.125*log2(e))
__device__ __half g_k   [TOK * DIM];   // K
__device__ __half g_v   [TOK * DIM];   // V
__device__ __half g_attn[TOK * DIM];
__device__ __half g_xln2[TOK * DIM];
__device__ __half g_h   [TOK * MLPD];
__device__ __half g_wqkv[3 * DIM * DIM];
__device__ __half g_wout[DIM * DIM];
__device__ __half g_w1  [MLPD * DIM];
__device__ __half g_w2  [DIM * MLPD];

// ---------------- helpers ----------------
__device__ __forceinline__ uint32_t cvt2h(float x, float y) {
    __half2 h = __floats2half2_rn(x, y);
    return *(uint32_t*)&h;
}

__device__ __forceinline__ float ex2a(float x) {
    float y;
    asm("ex2.approx.ftz.f32 %0, %1;" : "=f"(y) : "f"(x));
    return y;
}
__device__ __forceinline__ float rcpa(float x) {
    float y;
    asm("rcp.approx.ftz.f32 %0, %1;" : "=f"(y) : "f"(x));
    return y;
}
__device__ __forceinline__ float silu_fast(float x) {
    // x * sigmoid(x) = x / (1 + 2^(-x*log2e))
    return x * rcpa(1.0f + ex2a(-1.44269504f * x));
}

__device__ __forceinline__ void mma_f16(float* d,
    uint32_t a0, uint32_t a1, uint32_t a2, uint32_t a3,
    uint32_t b0, uint32_t b1)
{
    asm volatile(
        "mma.sync.aligned.m16n8k16.row.col.f32.f16.f16.f32 "
        "{%0,%1,%2,%3}, {%4,%5,%6,%7}, {%8,%9}, {%0,%1,%2,%3};"
        : "+f"(d[0]), "+f"(d[1]), "+f"(d[2]), "+f"(d[3])
        : "r"(a0), "r"(a1), "r"(a2), "r"(a3), "r"(b0), "r"(b1));
}

#define LDSM4(R0,R1,R2,R3,ADDR) \
    asm volatile("ldmatrix.sync.aligned.m8n8.x4.shared.b16 {%0,%1,%2,%3}, [%4];" \
        : "=r"(R0), "=r"(R1), "=r"(R2), "=r"(R3) : "r"(ADDR))
#define LDSM4T(R0,R1,R2,R3,ADDR) \
    asm volatile("ldmatrix.sync.aligned.m8n8.x4.trans.shared.b16 {%0,%1,%2,%3}, [%4];" \
        : "=r"(R0), "=r"(R1), "=r"(R2), "=r"(R3) : "r"(ADDR))

#define CP16(dst, src) \
    asm volatile("cp.async.ca.shared.global [%0], [%1], 16;" :: "r"(dst), "l"(src) : "memory")
#define CP_COMMIT() asm volatile("cp.async.commit_group;" ::: "memory")
#define CP_WAIT2()  asm volatile("cp.async.wait_group 2;" ::: "memory")
#define CP_WAIT1()  asm volatile("cp.async.wait_group 1;" ::: "memory")

// ---------------- merged weight convert (fp32 -> fp16) ----------------
#define CB0 (3 * DIM * DIM / 4)
#define CB1 (CB0 + DIM * DIM / 4)
#define CB2 (CB1 + MLPD * DIM / 4)
#define CB3 (CB2 + DIM * MLPD / 4)

__global__ __launch_bounds__(256) void conv_all(
    const float* __restrict__ s0, const float* __restrict__ s1,
    const float* __restrict__ s2, const float* __restrict__ s3,
    __half* __restrict__ d0, __half* __restrict__ d1,
    __half* __restrict__ d2, __half* __restrict__ d3)
{
    int i0 = blockIdx.x * 1024 + threadIdx.x;
    #pragma unroll
    for (int k2 = 0; k2 < 4; ++k2) {
        int i = i0 + k2 * 256;
        if (i < CB3) {
            const float* sp; __half* dp; int off;
            if (i < CB0)      { sp = s0; dp = d0; off = i; }
            else if (i < CB1) { sp = s1; dp = d1; off = i - CB0; }
            else if (i < CB2) { sp = s2; dp = d2; off = i - CB1; }
            else              { sp = s3; dp = d3; off = i - CB2; }
            float4 v = ((const float4*)sp)[off];
            ((uint2*)dp)[off] = make_uint2(cvt2h(v.x, v.y), cvt2h(v.z, v.w));
        }
    }
}

// ---------------- LayerNorm, warp-per-row ----------------
__global__ __launch_bounds__(256) void ln_kernel(
    const float* __restrict__ x, const float* __restrict__ w,
    const float* __restrict__ b, __half* __restrict__ o)
{
    int warp = threadIdx.x >> 5, lane = threadIdx.x & 31;
    int row = blockIdx.x * 8 + warp;
    const float4* xr = (const float4*)(x + (size_t)row * DIM);
    float4 v[8];
    float s = 0.f, sq = 0.f;
    #pragma unroll
    for (int i = 0; i < 8; i++) {
        v[i] = xr[lane + i * 32];
        s  += v[i].x + v[i].y + v[i].z + v[i].w;
        sq += v[i].x*v[i].x + v[i].y*v[i].y + v[i].z*v[i].z + v[i].w*v[i].w;
    }
    #pragma unroll
    for (int of = 16; of > 0; of >>= 1) {
        s  += __shfl_xor_sync(0xffffffffu, s,  of);
        sq += __shfl_xor_sync(0xffffffffu, sq, of);
    }
    float mean = s * (1.0f / DIM);
    float rstd = rsqrtf(sq * (1.0f / DIM) - mean * mean + 1e-5f);
    uint2* orow = (uint2*)o + (size_t)row * (DIM / 4);
    #pragma unroll
    for (int i = 0; i < 8; i++) {
        int idx = lane + i * 32;
        float4 wv = ((const float4*)w)[idx];
        float4 bv = ((const float4*)b)[idx];
        float ox = (v[i].x - mean) * rstd * wv.x + bv.x;
        float oy = (v[i].y - mean) * rstd * wv.y + bv.y;
        float oz = (v[i].z - mean) * rstd * wv.z + bv.z;
        float ow = (v[i].w - mean) * rstd * wv.w + bv.w;
        orow[idx] = make_uint2(cvt2h(ox, oy), cvt2h(oz, ow));
    }
}

// ---------------- NT GEMM fp16, KT=32, 4-stage cp.async, ldmatrix ----------
#define EPI_NONE      0
#define EPI_BIAS_RES  1
#define EPI_SILU_H    2
#define EPI_QKV       3

#define WST2 20
#define PLW2 (128 * WST2)
#define STGW2 (2 * PLW2)
#define NSTAGE 4
#define GEMM_SMEM (NSTAGE * STGW2 * 4)   // 81920

template <int EPI>
__global__ __launch_bounds__(256, 2) void gemm_f16(
    const __half* __restrict__ A, const __half* __restrict__ W,
    const float* __restrict__ bias, const float* __restrict__ res,
    float* __restrict__ C,
    __half* __restrict__ H0, __half* __restrict__ H1, __half* __restrict__ H2,
    int M, int N, int K)
{
    extern __shared__ __align__(16) uint32_t smw[];
    uint32_t sbase = (uint32_t)__cvta_generic_to_shared(smw);

    int tid  = threadIdx.x;
    int warp = tid >> 5, lane = tid & 31;
    int bm   = blockIdx.y * 128;
    int bn   = blockIdx.x * 128;
    int wm   = (warp & 1) * 64;
    int wn   = (warp >> 1) * 32;
    int gid  = lane >> 2, tig = lane & 3;

    int lrow  = tid >> 1;
    int lh    = tid & 1;
    const __half* pA = A + (size_t)(bm + lrow) * K + lh * 16;
    const __half* pW = W + (size_t)(bn + lrow) * K + lh * 16;
    uint32_t dstb = (uint32_t)(lrow * WST2 + lh * 8) * 4;

    uint32_t a_off = (uint32_t)(((wm + (lane & 15)) * WST2 + (lane >> 4) * 4) * 4);
    uint32_t b_off = (uint32_t)(((wn + ((lane >> 4) & 1) * 8 + (lane & 7)) * WST2
                                 + ((lane >> 3) & 1) * 4) * 4);

    float acc[4][4][4];
    #pragma unroll
    for (int i = 0; i < 4; i++)
        #pragma unroll
        for (int j = 0; j < 4; j++)
            #pragma unroll
            for (int r = 0; r < 4; r++) acc[i][j][r] = 0.f;

    int ntiles = K >> 5;

    auto issue = [&](int t) {
        uint32_t base = sbase + ((t % NSTAGE) * STGW2) * 4 + dstb;
        const __half* a = pA + (size_t)t * 32;
        const __half* w = pW + (size_t)t * 32;
        CP16(base,               a);
        CP16(base + 16,          a + 8);
        CP16(base + PLW2*4,      w);
        CP16(base + PLW2*4 + 16, w + 8);
    };

    issue(0); CP_COMMIT();
    issue(1); CP_COMMIT();
    issue(2); CP_COMMIT();

    for (int t = 0; t < ntiles; ++t) {
        CP_WAIT2();
        __syncthreads();
        if (t + 3 < ntiles) issue(t + 3);
        CP_COMMIT();
        uint32_t stb = sbase + ((t % NSTAGE) * STGW2) * 4;

        #pragma unroll
        for (int kc = 0; kc < 2; ++kc) {
            uint32_t kcb = kc * 32;
            uint32_t bw[4][2];
            #pragma unroll
            for (int p = 0; p < 2; ++p) {
                uint32_t r0, r1, r2, r3;
                LDSM4(r0, r1, r2, r3, stb + PLW2*4 + b_off + p * 16 * WST2 * 4 + kcb);
                bw[2*p][0] = r0; bw[2*p][1] = r1; bw[2*p+1][0] = r2; bw[2*p+1][1] = r3;
            }
            #pragma unroll
            for (int mt = 0; mt < 4; ++mt) {
                uint32_t a0, a1, a2, a3;
                LDSM4(a0, a1, a2, a3, stb + a_off + mt * 16 * WST2 * 4 + kcb);
                #pragma unroll
                for (int nt = 0; nt < 4; ++nt)
                    mma_f16(acc[mt][nt], a0, a1, a2, a3, bw[nt][0], bw[nt][1]);
            }
        }
    }

    // ---- epilogue ----
    #pragma unroll
    for (int mt = 0; mt < 4; ++mt) {
        #pragma unroll
        for (int nt = 0; nt < 4; ++nt) {
            int row = bm + wm + mt * 16 + gid;
            int col = bn + wn + nt * 8 + tig * 2;
            float2 v0 = make_float2(acc[mt][nt][0], acc[mt][nt][1]);
            float2 v1 = make_float2(acc[mt][nt][2], acc[mt][nt][3]);
            if (EPI == EPI_BIAS_RES || EPI == EPI_SILU_H) {
                float bx = bias[col], by = bias[col + 1];
                v0.x += bx; v0.y += by; v1.x += bx; v1.y += by;
            }
            if (EPI == EPI_BIAS_RES) {
                float2 r0 = *(const float2*)(res + (size_t)row * N + col);
                float2 r1 = *(const float2*)(res + (size_t)(row + 8) * N + col);
                v0.x += r0.x; v0.y += r0.y; v1.x += r1.x; v1.y += r1.y;
                *(float2*)(C + (size_t)row * N + col)       = v0;
                *(float2*)(C + (size_t)(row + 8) * N + col) = v1;
            } else if (EPI == EPI_SILU_H) {
                v0.x = silu_fast(v0.x); v0.y = silu_fast(v0.y);
                v1.x = silu_fast(v1.x); v1.y = silu_fast(v1.y);
                *(uint32_t*)(H0 + (size_t)row * N + col)       = cvt2h(v0.x, v0.y);
                *(uint32_t*)(H0 + (size_t)(row + 8) * N + col) = cvt2h(v1.x, v1.y);
            } else if (EPI == EPI_QKV) {
                int region = col >> 10;
                int colr   = col & 1023;
                __half* dst = (region == 0) ? H0 : (region == 1) ? H1 : H2;
                float sc = (region == 0) ? 0.125f * 1.44269504f : 1.0f;
                *(uint32_t*)(dst + (size_t)row * DIM + colr) =
                    cvt2h(v0.x * sc, v0.y * sc);
                *(uint32_t*)(dst + (size_t)(row + 8) * DIM + colr) =
                    cvt2h(v1.x * sc, v1.y * sc);
            } else {
                *(float2*)(C + (size_t)row * N + col)       = v0;
                *(float2*)(C + (size_t)(row + 8) * N + col) = v1;
            }
        }
    }
}

// ---------------- Flash attention fp16: cp.async K/V ring + trans-V --------
#define AST 36
#define WQW (128 * AST)
#define KVSTG (128 * AST)
#define NKV 3
#define ATTN_WORDS (WQW + NKV * KVSTG)
#define ATTN_SM_BYTES (ATTN_WORDS * 4)    // 73728

__global__ __launch_bounds__(256, 2) void attn_f16(
    const __half* __restrict__ Qg, const __half* __restrict__ Kg,
    const __half* __restrict__ Vg, __half* __restrict__ o)
{
    extern __shared__ uint32_t smw[];
    uint32_t sbase = (uint32_t)__cvta_generic_to_shared(smw);

    int tid  = threadIdx.x;
    int warp = tid >> 5, lane = tid & 31;
    int gid  = lane >> 2, tig = lane & 3;
    int qrow0 = warp * 16;

    int qb = blockIdx.x;
    int b  = blockIdx.y >> 4;
    int h  = blockIdx.y & 15;

    uint32_t aoff  = (uint32_t)((((lane & 15)) * AST + (lane >> 4) * 4) * 4);
    uint32_t kboff = (uint32_t)(((((lane >> 4) & 1) * 8 + (lane & 7)) * AST
                                 + ((lane >> 3) & 1) * 4) * 4);
    uint32_t vboff = (uint32_t)((((lane & 7) + ((lane >> 3) & 1) * 8) * AST
                                 + ((lane >> 4) & 1) * 4) * 4);

    const __half* qg = Qg + (size_t)(b * SEQ + qb * 128) * DIM + h * HD;
    const __half* kbase = Kg + (size_t)(b * SEQ) * DIM + h * HD;
    const __half* vbase = Vg + (size_t)(b * SEQ) * DIM + h * HD;

    auto issueKV = [&](int jb, int st) {
        const __half* kg = kbase + (size_t)(jb * 64) * DIM;
        const __half* vg = vbase + (size_t)(jb * 64) * DIM;
        uint32_t kst = sbase + (WQW + st * KVSTG) * 4;
        uint32_t vst = kst + 64 * AST * 4;
        #pragma unroll
        for (int c = 0; c < 2; ++c) {
            int ch = tid + c * 256;
            int r = ch >> 3, cw = ch & 7;
            uint32_t off = (uint32_t)(r * AST + cw * 4) * 4;
            CP16(kst + off, kg + (size_t)r * DIM + cw * 8);
            CP16(vst + off, vg + (size_t)r * DIM + cw * 8);
        }
    };

    // prologue
    issueKV(0, 0);
    #pragma unroll
    for (int c = 0; c < 4; ++c) {
        int ch = tid + c * 256;
        int r = ch >> 3, cw = ch & 7;
        CP16(sbase + (uint32_t)(r * AST + cw * 4) * 4, qg + (size_t)r * DIM + cw * 8);
    }
    CP_COMMIT();
    issueKV(1, 1);
    CP_COMMIT();

    CP_WAIT1();
    __syncthreads();
    uint32_t qf[4][4];
    #pragma unroll
    for (int kcx = 0; kcx < 4; ++kcx)
        LDSM4(qf[kcx][0], qf[kcx][1], qf[kcx][2], qf[kcx][3],
              sbase + (uint32_t)(qrow0 * AST) * 4 + aoff + kcx * 32);

    float m0 = -1e30f, m1 = -1e30f, l0r = 0.f, l1r = 0.f;
    float oacc[8][4];
    #pragma unroll
    for (int nt = 0; nt < 8; nt++)
        #pragma unroll
        for (int r = 0; r < 4; r++) oacc[nt][r] = 0.f;

    for (int jb = 0; jb < SEQ / 64; ++jb) {
        if (jb > 0) { CP_WAIT1(); __syncthreads(); }
        if (jb + 2 < SEQ / 64) issueKV(jb + 2, (jb + 2) % NKV);
        CP_COMMIT();

        uint32_t kst4 = sbase + (WQW + (jb % NKV) * KVSTG) * 4;
        uint32_t vst4 = kst4 + 64 * AST * 4;

        // ---- S = Q K^T (base-2 scaled) ----
        float s[8][4];
        #pragma unroll
        for (int nt = 0; nt < 8; nt++)
            #pragma unroll
            for (int r = 0; r < 4; r++) s[nt][r] = 0.f;

        #pragma unroll
        for (int kcx = 0; kcx < 4; ++kcx) {
            uint32_t kcb = kcx * 32;
            #pragma unroll
            for (int p = 0; p < 4; ++p) {
                uint32_t r0, r1, r2, r3;
                LDSM4(r0, r1, r2, r3, kst4 + p * 16 * AST * 4 + kboff + kcb);
                mma_f16(s[2*p],   qf[kcx][0], qf[kcx][1], qf[kcx][2], qf[kcx][3], r0, r1);
                mma_f16(s[2*p+1], qf[kcx][0], qf[kcx][1], qf[kcx][2], qf[kcx][3], r2, r3);
            }
        }

        // ---- online softmax (bare MUFU ex2) ----
        float mc0 = s[0][0], mc1 = s[0][2];
        #pragma unroll
        for (int nt = 0; nt < 8; ++nt) {
            mc0 = fmaxf(mc0, fmaxf(s[nt][0], s[nt][1]));
            mc1 = fmaxf(mc1, fmaxf(s[nt][2], s[nt][3]));
        }
        mc0 = fmaxf(mc0, __shfl_xor_sync(0xffffffffu, mc0, 1));
        mc0 = fmaxf(mc0, __shfl_xor_sync(0xffffffffu, mc0, 2));
        mc1 = fmaxf(mc1, __shfl_xor_sync(0xffffffffu, mc1, 1));
        mc1 = fmaxf(mc1, __shfl_xor_sync(0xffffffffu, mc1, 2));
        float mn0 = fmaxf(m0, mc0), mn1 = fmaxf(m1, mc1);
        float f0 = ex2a(m0 - mn0), f1 = ex2a(m1 - mn1);
        m0 = mn0; m1 = mn1;

        float ps0 = 0.f, ps1 = 0.f;
        #pragma unroll
        for (int nt = 0; nt < 8; ++nt) {
            float p0 = ex2a(s[nt][0] - m0);
            float p1 = ex2a(s[nt][1] - m0);
            float p2 = ex2a(s[nt][2] - m1);
            float p3 = ex2a(s[nt][3] - m1);
            ps0 += p0 + p1; ps1 += p2 + p3;
            s[nt][0] = p0; s[nt][1] = p1; s[nt][2] = p2; s[nt][3] = p3;
        }
        ps0 += __shfl_xor_sync(0xffffffffu, ps0, 1);
        ps0 += __shfl_xor_sync(0xffffffffu, ps0, 2);
        ps1 += __shfl_xor_sync(0xffffffffu, ps1, 1);
        ps1 += __shfl_xor_sync(0xffffffffu, ps1, 2);
        l0r = l0r * f0 + ps0;
        l1r = l1r * f1 + ps1;
        bool need = (f0 != 1.0f) || (f1 != 1.0f);
        if (__any_sync(0xffffffffu, need)) {
            #pragma unroll
            for (int nt = 0; nt < 8; ++nt) {
                oacc[nt][0] *= f0; oacc[nt][1] *= f0;
                oacc[nt][2] *= f1; oacc[nt][3] *= f1;
            }
        }

        // ---- O += P V (register repack; V via trans-ldmatrix) ----
        #pragma unroll
        for (int kcx = 0; kcx < 4; ++kcx) {
            uint32_t pa0 = cvt2h(s[2*kcx][0],   s[2*kcx][1]);
            uint32_t pa1 = cvt2h(s[2*kcx][2],   s[2*kcx][3]);
            uint32_t pa2 = cvt2h(s[2*kcx+1][0], s[2*kcx+1][1]);
            uint32_t pa3 = cvt2h(s[2*kcx+1][2], s[2*kcx+1][3]);
            #pragma unroll
            for (int p = 0; p < 4; ++p) {
                uint32_t r0, r1, r2, r3;
                LDSM4T(r0, r1, r2, r3,
                       vst4 + vboff + (uint32_t)(kcx * 16 * AST + p * 8) * 4);
                mma_f16(oacc[2*p],   pa0, pa1, pa2, pa3, r0, r1);
                mma_f16(oacc[2*p+1], pa0, pa1, pa2, pa3, r2, r3);
            }
        }
    }

    float inv0 = rcpa(l0r), inv1 = rcpa(l1r);
    int grow0 = b * SEQ + qb * 128 + qrow0 + gid;
    #pragma unroll
    for (int nt = 0; nt < 8; ++nt) {
        int col = h * HD + nt * 8 + tig * 2;
        *(uint32_t*)(o + (size_t)grow0 * DIM + col) =
            cvt2h(oacc[nt][0] * inv0, oacc[nt][1] * inv0);
        *(uint32_t*)(o + (size_t)(grow0 + 8) * DIM + col) =
            cvt2h(oacc[nt][2] * inv1, oacc[nt][3] * inv1);
    }
}

// ---------------- launch ----------------
extern "C" void kernel_launch(void* const* d_in, const int* in_sizes, int n_in,
                              void* d_out, int out_size)
{
    const float* x     = (const float*)d_in[0];
    const float* qkv_w = (const float*)d_in[1];
    const float* out_w = (const float*)d_in[2];
    const float* out_b = (const float*)d_in[3];
    const float* ff_w1 = (const float*)d_in[4];
    const float* ff_b1 = (const float*)d_in[5];
    const float* ff_w2 = (const float*)d_in[6];
    const float* ff_b2 = (const float*)d_in[7];
    const float* ln1_w = (const float*)d_in[8];
    const float* ln1_b = (const float*)d_in[9];
    const float* ln2_w = (const float*)d_in[10];
    const float* ln2_b = (const float*)d_in[11];
    float* out = (float*)d_out;

    float *x1;
    __half *xln, *q, *k, *v, *attn, *xln2, *hbuf;
    __half *wq, *wo, *w1, *w2;
    cudaGetSymbolAddress((void**)&x1,   g_x1);
    cudaGetSymbolAddress((void**)&xln,  g_xln);
    cudaGetSymbolAddress((void**)&q,    g_q);
    cudaGetSymbolAddress((void**)&k,    g_k);
    cudaGetSymbolAddress((void**)&v,    g_v);
    cudaGetSymbolAddress((void**)&attn, g_attn);
    cudaGetSymbolAddress((void**)&xln2, g_xln2);
    cudaGetSymbolAddress((void**)&hbuf, g_h);
    cudaGetSymbolAddress((void**)&wq,   g_wqkv);
    cudaGetSymbolAddress((void**)&wo,   g_wout);
    cudaGetSymbolAddress((void**)&w1,   g_w1);
    cudaGetSymbolAddress((void**)&w2,   g_w2);

    cudaFuncSetAttribute(gemm_f16<EPI_QKV>,
        cudaFuncAttributeMaxDynamicSharedMemorySize, GEMM_SMEM);
    cudaFuncSetAttribute(gemm_f16<EPI_BIAS_RES>,
        cudaFuncAttributeMaxDynamicSharedMemorySize, GEMM_SMEM);
    cudaFuncSetAttribute(gemm_f16<EPI_SILU_H>,
        cudaFuncAttributeMaxDynamicSharedMemorySize, GEMM_SMEM);
    cudaFuncSetAttribute(attn_f16,
        cudaFuncAttributeMaxDynamicSharedMemorySize, ATTN_SM_BYTES);

    // 0. convert all weights to fp16 (single launch)
    conv_all<<<(CB3 + 1023) / 1024, 256>>>(qkv_w, out_w, ff_w1, ff_w2, wq, wo, w1, w2);

    // 1. LN1 -> fp16
    ln_kernel<<<TOK / 8, 256>>>(x, ln1_w, ln1_b, xln);
    // 2. QKV -> fp16 q(scaled)/k/v
    gemm_f16<EPI_QKV><<<dim3(3 * DIM / 128, TOK / 128), 256, GEMM_SMEM>>>(
        xln, wq, nullptr, nullptr, nullptr, q, k, v, TOK, 3 * DIM, DIM);
    // 3. attention -> fp16
    attn_f16<<<dim3(SEQ / 128, 2 * NHEAD), 256, ATTN_SM_BYTES>>>(q, k, v, attn);
    // 4. x1 = x + attn @ out_w^T + out_b -> fp32
    gemm_f16<EPI_BIAS_RES><<<dim3(DIM / 128, TOK / 128), 256, GEMM_SMEM>>>(
        attn, wo, out_b, x, x1, nullptr, nullptr, nullptr, TOK, DIM, DIM);
    // 5. LN2 -> fp16
    ln_kernel<<<TOK / 8, 256>>>(x1, ln2_w, ln2_b, xln2);
    // 6. h = silu(...) -> fp16
    gemm_f16<EPI_SILU_H><<<dim3(MLPD / 128, TOK / 128), 256, GEMM_SMEM>>>(
        xln2, w1, ff_b1, nullptr, nullptr, hbuf, nullptr, nullptr, TOK, MLPD, DIM);
    // 7. out = x1 + h @ ff_w2^T + ff_b2 -> fp32
    gemm_f16<EPI_BIAS_RES><<<dim3(DIM / 128, TOK / 128), 256, GEMM_SMEM>>>(
        hbuf, w2, ff_b2, x1, out, nullptr, nullptr, nullptr, TOK, DIM, MLPD);
}